// round 1
// baseline (speedup 1.0000x reference)
#include <cuda_runtime.h>

#define BB 4
#define CIN 64
#define HH 128
#define WW 128
#define HID 384
#define COUT 64
#define NPATCH 256          // 16 x 16
#define NP 52608            // params per patch
#define P2OFF 24576         // K2 offset (hidden*Cin)
#define P3OFF 28032         // W3 offset (+hidden*9)
#define EPSV 1e-5f

// scratch (static __device__ arrays; no runtime allocation)
__device__ float g_wt[(size_t)BB * NPATCH * NP];        // [b][patch][param]  ~215MB
__device__ float g_h1[(size_t)BB * HID * HH * WW];      // ~100MB
__device__ float g_h2[(size_t)BB * HID * HH * WW];      // ~100MB

// ---------------------------------------------------------------------------
// Transpose w [B][NP][256(fg)] -> g_wt [B][256(fg)][NP]
// ---------------------------------------------------------------------------
__global__ __launch_bounds__(256) void k_transpose(const float* __restrict__ w) {
    __shared__ float tile[32][33];
    int b = blockIdx.z;
    size_t base = (size_t)b * NP * 256;
    int g0 = blockIdx.x * 32;   // fg dim (256 total)
    int p0 = blockIdx.y * 32;   // param dim (52608 total, /32 = 1644)
    for (int i = threadIdx.y; i < 32; i += 8)
        tile[i][threadIdx.x] = w[base + (size_t)(p0 + i) * 256 + g0 + threadIdx.x];
    __syncthreads();
    for (int i = threadIdx.y; i < 32; i += 8)
        g_wt[base + (size_t)(g0 + i) * NP + p0 + threadIdx.x] = tile[threadIdx.x][i];
}

// ---------------------------------------------------------------------------
// Stage 1: per-patch pointwise  h1 = relu6(bn1(W1 @ x_patch))
// One CTA per patch. 256 threads: thread = (o_l = tid/8 in [0,32), 8 pixels)
// ---------------------------------------------------------------------------
__global__ __launch_bounds__(256) void k_stage1(
    const float* __restrict__ x,
    const float* __restrict__ g1, const float* __restrict__ b1,
    const float* __restrict__ m1, const float* __restrict__ v1)
{
    __shared__ float xs[64][64];   // [c][px]
    __shared__ float ws[32][64];   // [o_local][c]
    int blk = blockIdx.x;
    int b = blk >> 8;
    int pid = blk & 255;
    int f = pid >> 4, g = pid & 15;
    int tid = threadIdx.x;
    const float* Wb = g_wt + (size_t)(b * NPATCH + pid) * NP;

    for (int idx = tid; idx < 64 * 64; idx += 256) {
        int c = idx >> 6, px = idx & 63;
        int p = px >> 3, q = px & 7;
        xs[c][px] = x[(((size_t)b * CIN + c) * HH + f * 8 + p) * WW + g * 8 + q];
    }

    int o_l = tid >> 3;
    int px0 = (tid & 7) * 8;   // full pixel row p = tid&7

    for (int ot = 0; ot < 12; ot++) {
        __syncthreads();
        for (int idx = tid; idx < 32 * 64; idx += 256)
            ws[idx >> 6][idx & 63] = Wb[(ot * 32 + (idx >> 6)) * 64 + (idx & 63)];
        __syncthreads();

        float4 a0 = {0.f,0.f,0.f,0.f}, a1 = {0.f,0.f,0.f,0.f};
        #pragma unroll 8
        for (int c = 0; c < 64; c++) {
            float wv = ws[o_l][c];
            float4 x0 = *(const float4*)&xs[c][px0];
            float4 x1 = *(const float4*)&xs[c][px0 + 4];
            a0.x += wv * x0.x; a0.y += wv * x0.y; a0.z += wv * x0.z; a0.w += wv * x0.w;
            a1.x += wv * x1.x; a1.y += wv * x1.y; a1.z += wv * x1.z; a1.w += wv * x1.w;
        }
        int o = ot * 32 + o_l;
        float inv = g1[o] * rsqrtf(v1[o] + EPSV);
        float sh  = b1[o] - m1[o] * inv;
        a0.x = fminf(fmaxf(a0.x * inv + sh, 0.f), 6.f);
        a0.y = fminf(fmaxf(a0.y * inv + sh, 0.f), 6.f);
        a0.z = fminf(fmaxf(a0.z * inv + sh, 0.f), 6.f);
        a0.w = fminf(fmaxf(a0.w * inv + sh, 0.f), 6.f);
        a1.x = fminf(fmaxf(a1.x * inv + sh, 0.f), 6.f);
        a1.y = fminf(fmaxf(a1.y * inv + sh, 0.f), 6.f);
        a1.z = fminf(fmaxf(a1.z * inv + sh, 0.f), 6.f);
        a1.w = fminf(fmaxf(a1.w * inv + sh, 0.f), 6.f);

        int p = px0 >> 3;
        float* dst = &g_h1[(((size_t)b * HID + o) * HH + f * 8 + p) * WW + g * 8];
        *(float4*)dst = a0;
        *(float4*)(dst + 4) = a1;
    }
}

// ---------------------------------------------------------------------------
// Stage 2: per-patch depthwise 3x3 with reflect halo, bn2, relu6
// ---------------------------------------------------------------------------
__global__ __launch_bounds__(256) void k_stage2(
    const float* __restrict__ g2, const float* __restrict__ b2,
    const float* __restrict__ m2, const float* __restrict__ v2)
{
    __shared__ float hs[8][10][10];
    __shared__ float ks[8][9];
    int blk = blockIdx.x;
    int b = blk >> 8;
    int pid = blk & 255;
    int f = pid >> 4, g = pid & 15;
    int tid = threadIdx.x;
    const float* Wb = g_wt + (size_t)(b * NPATCH + pid) * NP + P2OFF;
    int y0 = f * 8, x0c = g * 8;

    for (int cc = 0; cc < 48; cc++) {
        int ch0 = cc * 8;
        __syncthreads();
        for (int idx = tid; idx < 800; idx += 256) {
            int cl = idx / 100;
            int rem = idx - cl * 100;
            int r = rem / 10, col = rem - (rem / 10) * 10;
            int yy = y0 + r - 1;
            int xx = x0c + col - 1;
            yy = yy < 0 ? -yy : (yy >= HH ? 2 * HH - 2 - yy : yy);   // reflect
            xx = xx < 0 ? -xx : (xx >= WW ? 2 * WW - 2 - xx : xx);
            hs[cl][r][col] = g_h1[(((size_t)b * HID + ch0 + cl) * HH + yy) * WW + xx];
        }
        if (tid < 72) ks[tid / 9][tid % 9] = Wb[(ch0 + tid / 9) * 9 + (tid % 9)];
        __syncthreads();

        for (int t = tid; t < 512; t += 256) {
            int cl = t >> 6;
            int px = t & 63;
            int p = px >> 3, q = px & 7;
            float acc = 0.f;
            #pragma unroll
            for (int dy = 0; dy < 3; dy++)
                #pragma unroll
                for (int dx = 0; dx < 3; dx++)
                    acc += hs[cl][p + dy][q + dx] * ks[cl][dy * 3 + dx];
            int ch = ch0 + cl;
            float inv = g2[ch] * rsqrtf(v2[ch] + EPSV);
            float sh  = b2[ch] - m2[ch] * inv;
            acc = fminf(fmaxf(acc * inv + sh, 0.f), 6.f);
            g_h2[(((size_t)b * HID + ch) * HH + y0 + p) * WW + x0c + q] = acc;
        }
    }
}

// ---------------------------------------------------------------------------
// Stage 3: per-patch pointwise  out = x + bn3(W3 @ h2_patch)
// thread = (co_l = tid/8 in [0,32) -> co {co_l, co_l+32}, 8 pixels)
// ---------------------------------------------------------------------------
__global__ __launch_bounds__(256) void k_stage3(
    const float* __restrict__ x,
    const float* __restrict__ g3, const float* __restrict__ b3,
    const float* __restrict__ m3, const float* __restrict__ v3,
    float* __restrict__ out)
{
    __shared__ float hs[64][64];   // [k_chunk][px]
    __shared__ float ws[64][64];   // [co][k_chunk]
    int blk = blockIdx.x;
    int b = blk >> 8;
    int pid = blk & 255;
    int f = pid >> 4, g = pid & 15;
    int tid = threadIdx.x;
    const float* Wb = g_wt + (size_t)(b * NPATCH + pid) * NP + P3OFF;

    int co_l = tid >> 3;
    int px0 = (tid & 7) * 8;

    float4 a00 = {0.f,0.f,0.f,0.f}, a01 = {0.f,0.f,0.f,0.f};
    float4 a10 = {0.f,0.f,0.f,0.f}, a11 = {0.f,0.f,0.f,0.f};

    for (int kt = 0; kt < 6; kt++) {
        __syncthreads();
        for (int idx = tid; idx < 4096; idx += 256) {
            int kc = idx >> 6, px = idx & 63;
            int p = px >> 3, q = px & 7;
            hs[kc][px] = g_h2[(((size_t)b * HID + kt * 64 + kc) * HH + f * 8 + p) * WW + g * 8 + q];
        }
        for (int idx = tid; idx < 4096; idx += 256) {
            int co = idx >> 6, kc = idx & 63;
            ws[co][kc] = Wb[co * HID + kt * 64 + kc];
        }
        __syncthreads();

        #pragma unroll 4
        for (int kc = 0; kc < 64; kc++) {
            float w0 = ws[co_l][kc];
            float w1 = ws[co_l + 32][kc];
            float4 x0 = *(const float4*)&hs[kc][px0];
            float4 x1 = *(const float4*)&hs[kc][px0 + 4];
            a00.x += w0 * x0.x; a00.y += w0 * x0.y; a00.z += w0 * x0.z; a00.w += w0 * x0.w;
            a01.x += w0 * x1.x; a01.y += w0 * x1.y; a01.z += w0 * x1.z; a01.w += w0 * x1.w;
            a10.x += w1 * x0.x; a10.y += w1 * x0.y; a10.z += w1 * x0.z; a10.w += w1 * x0.w;
            a11.x += w1 * x1.x; a11.y += w1 * x1.y; a11.z += w1 * x1.z; a11.w += w1 * x1.w;
        }
    }

    int p = px0 >> 3;
    // co = co_l
    {
        int co = co_l;
        float inv = g3[co] * rsqrtf(v3[co] + EPSV);
        float sh  = b3[co] - m3[co] * inv;
        size_t base = (((size_t)b * COUT + co) * HH + f * 8 + p) * WW + g * 8;
        float4 xr0 = *(const float4*)&x[base];
        float4 xr1 = *(const float4*)&x[base + 4];
        float4 r0, r1;
        r0.x = xr0.x + (a00.x * inv + sh); r0.y = xr0.y + (a00.y * inv + sh);
        r0.z = xr0.z + (a00.z * inv + sh); r0.w = xr0.w + (a00.w * inv + sh);
        r1.x = xr1.x + (a01.x * inv + sh); r1.y = xr1.y + (a01.y * inv + sh);
        r1.z = xr1.z + (a01.z * inv + sh); r1.w = xr1.w + (a01.w * inv + sh);
        *(float4*)&out[base] = r0;
        *(float4*)&out[base + 4] = r1;
    }
    // co = co_l + 32
    {
        int co = co_l + 32;
        float inv = g3[co] * rsqrtf(v3[co] + EPSV);
        float sh  = b3[co] - m3[co] * inv;
        size_t base = (((size_t)b * COUT + co) * HH + f * 8 + p) * WW + g * 8;
        float4 xr0 = *(const float4*)&x[base];
        float4 xr1 = *(const float4*)&x[base + 4];
        float4 r0, r1;
        r0.x = xr0.x + (a10.x * inv + sh); r0.y = xr0.y + (a10.y * inv + sh);
        r0.z = xr0.z + (a10.z * inv + sh); r0.w = xr0.w + (a10.w * inv + sh);
        r1.x = xr1.x + (a11.x * inv + sh); r1.y = xr1.y + (a11.y * inv + sh);
        r1.z = xr1.z + (a11.z * inv + sh); r1.w = xr1.w + (a11.w * inv + sh);
        *(float4*)&out[base] = r0;
        *(float4*)&out[base + 4] = r1;
    }
}

// ---------------------------------------------------------------------------
extern "C" void kernel_launch(void* const* d_in, const int* in_sizes, int n_in,
                              void* d_out, int out_size) {
    const float* x  = (const float*)d_in[0];
    const float* w  = (const float*)d_in[1];
    const float* g1 = (const float*)d_in[2];
    const float* b1 = (const float*)d_in[3];
    const float* m1 = (const float*)d_in[4];
    const float* v1 = (const float*)d_in[5];
    const float* g2 = (const float*)d_in[6];
    const float* b2 = (const float*)d_in[7];
    const float* m2 = (const float*)d_in[8];
    const float* v2 = (const float*)d_in[9];
    const float* g3 = (const float*)d_in[10];
    const float* b3 = (const float*)d_in[11];
    const float* m3 = (const float*)d_in[12];
    const float* v3 = (const float*)d_in[13];
    float* out = (float*)d_out;

    dim3 tb(32, 8);
    dim3 tg(256 / 32, NP / 32, BB);   // (8, 1644, 4)
    k_transpose<<<tg, tb>>>(w);
    k_stage1<<<BB * NPATCH, 256>>>(x, g1, b1, m1, v1);
    k_stage2<<<BB * NPATCH, 256>>>(g2, b2, m2, v2);
    k_stage3<<<BB * NPATCH, 256>>>(x, g3, b3, m3, v3, out);
}

// round 3
// speedup vs baseline: 1.6364x; 1.6364x over previous
#include <cuda_runtime.h>

#define BB 4
#define CIN 64
#define HH 128
#define WW 128
#define HID 384
#define COUT 64
#define NPATCH 256          // 16 x 16
#define NP 52608            // params per patch
#define P2OFF 24576         // K2 offset (hidden*Cin)
#define P3OFF 28032         // W3 offset (+hidden*9)
#define EPSV 1e-5f

// scratch (static __device__ arrays; no runtime allocation)
__device__ float g_wt[(size_t)BB * NPATCH * NP];          // [b][patch][param]  ~215MB
__device__ float g_h1[(size_t)BB * HID * HH * WW];        // image layout ~100MB
__device__ float g_h2[(size_t)BB * NPATCH * HID * 64];    // patch-major ~100MB

// ---- packed f32x2 helpers (B300: 3-reg FFMA is half-rate; FFMA2 restores full rate)
__device__ __forceinline__ unsigned long long pack2(float v) {
    unsigned long long r;
    asm("mov.b64 %0, {%1, %1};" : "=l"(r) : "f"(v));
    return r;
}
__device__ __forceinline__ void ffma2(unsigned long long& d, unsigned long long a,
                                      unsigned long long b) {
    asm("fma.rn.f32x2 %0, %1, %2, %0;" : "+l"(d) : "l"(a), "l"(b));
}
__device__ __forceinline__ void unpack2(unsigned long long v, float& lo, float& hi) {
    asm("mov.b64 {%0, %1}, %2;" : "=f"(lo), "=f"(hi) : "l"(v));
}

// ---------------------------------------------------------------------------
// Transpose w [B][NP][256(fg)] -> g_wt [B][256(fg)][NP]
// ---------------------------------------------------------------------------
__global__ __launch_bounds__(256) void k_transpose(const float* __restrict__ w) {
    __shared__ float tile[32][33];
    int b = blockIdx.z;
    size_t base = (size_t)b * NP * 256;
    int g0 = blockIdx.x * 32;   // fg dim (256 total)
    int p0 = blockIdx.y * 32;   // param dim (52608 total, /32 = 1644)
    for (int i = threadIdx.y; i < 32; i += 8)
        tile[i][threadIdx.x] = w[base + (size_t)(p0 + i) * 256 + g0 + threadIdx.x];
    __syncthreads();
    for (int i = threadIdx.y; i < 32; i += 8)
        g_wt[base + (size_t)(g0 + i) * NP + p0 + threadIdx.x] = tile[threadIdx.x][i];
}

// ---------------------------------------------------------------------------
// Stage 1: per-patch pointwise  h1 = relu6(bn1(W1 @ x_patch))
// 1 CTA per patch, 128 threads. Thread (i=tid/8, j=tid&7): tile 4o x 8px.
// o-chunks of 64 (6 chunks). Packed f32x2 FMA.
// ---------------------------------------------------------------------------
__global__ __launch_bounds__(128) void k_stage1(
    const float* __restrict__ x,
    const float* __restrict__ g1, const float* __restrict__ b1,
    const float* __restrict__ m1, const float* __restrict__ v1)
{
    __shared__ float xs[64][64];    // [c][px]    16KB
    __shared__ float ws[64][65];    // [o][c]
    int blk = blockIdx.x;           // 0..1023
    int b = blk >> 8, pid = blk & 255;
    int f = pid >> 4, g = pid & 15;
    int tid = threadIdx.x;
    int i = tid >> 3, j = tid & 7;
    int y0 = f * 8, x0 = g * 8;

    // load x patch: 64c x 64px = 1024 float4
    for (int idx = tid; idx < 1024; idx += 128) {
        int c = idx >> 4, v4 = idx & 15;
        int p = v4 >> 1, q4 = (v4 & 1) * 4;
        *(float4*)&xs[c][v4 * 4] =
            *(const float4*)&x[(((size_t)b * CIN + c) * HH + y0 + p) * WW + x0 + q4];
    }
    const float* Wb = g_wt + (size_t)(b * NPATCH + pid) * NP;

    for (int ot = 0; ot < 6; ot++) {
        __syncthreads();
        for (int idx = tid; idx < 4096; idx += 128) {
            int o = idx >> 6, c = idx & 63;
            ws[o][c] = Wb[(ot * 64 + o) * 64 + c];
        }
        __syncthreads();

        unsigned long long acc[4][4];
        #pragma unroll
        for (int a = 0; a < 4; a++)
            #pragma unroll
            for (int p2 = 0; p2 < 4; p2++) acc[a][p2] = 0ULL;

        #pragma unroll 8
        for (int c = 0; c < 64; c++) {
            ulonglong2 xa = *(const ulonglong2*)&xs[c][j * 8];
            ulonglong2 xb = *(const ulonglong2*)&xs[c][j * 8 + 4];
            #pragma unroll
            for (int oo = 0; oo < 4; oo++) {
                unsigned long long w2 = pack2(ws[i * 4 + oo][c]);
                ffma2(acc[oo][0], xa.x, w2);
                ffma2(acc[oo][1], xa.y, w2);
                ffma2(acc[oo][2], xb.x, w2);
                ffma2(acc[oo][3], xb.y, w2);
            }
        }

        #pragma unroll
        for (int oo = 0; oo < 4; oo++) {
            int o = ot * 64 + i * 4 + oo;
            float inv = g1[o] * rsqrtf(v1[o] + EPSV);
            float sh  = b1[o] - m1[o] * inv;
            float r[8];
            #pragma unroll
            for (int p2 = 0; p2 < 4; p2++) unpack2(acc[oo][p2], r[p2 * 2], r[p2 * 2 + 1]);
            #pragma unroll
            for (int q = 0; q < 8; q++)
                r[q] = fminf(fmaxf(r[q] * inv + sh, 0.f), 6.f);
            float* dst = &g_h1[(((size_t)b * HID + o) * HH + y0 + j) * WW + x0];
            *(float4*)dst       = make_float4(r[0], r[1], r[2], r[3]);
            *(float4*)(dst + 4) = make_float4(r[4], r[5], r[6], r[7]);
        }
    }
}

// ---------------------------------------------------------------------------
// Stage 2: per-patch depthwise 3x3 (reflect halo) + bn2 + relu6
// grid (1024 patches, 24 chgroups), 128 threads, 16 channels per CTA.
// Writes h2 patch-major [b][patch][ch][px].
// ---------------------------------------------------------------------------
__global__ __launch_bounds__(128) void k_stage2(
    const float* __restrict__ g2, const float* __restrict__ b2,
    const float* __restrict__ m2, const float* __restrict__ v2)
{
    __shared__ float hs[16][10][10];
    __shared__ float ks[16][9];
    int blk = blockIdx.x;
    int b = blk >> 8, pid = blk & 255;
    int f = pid >> 4, g = pid & 15;
    int ch0 = blockIdx.y * 16;
    int tid = threadIdx.x;
    int y0 = f * 8, x0 = g * 8;
    const float* Wb = g_wt + (size_t)(b * NPATCH + pid) * NP + P2OFF;

    for (int idx = tid; idx < 1600; idx += 128) {
        int cl = idx / 100;
        int rem = idx - cl * 100;
        int r = rem / 10, cc = rem - r * 10;
        int yy = y0 + r - 1;
        int xx = x0 + cc - 1;
        yy = yy < 0 ? -yy : (yy >= HH ? 2 * HH - 2 - yy : yy);   // reflect
        xx = xx < 0 ? -xx : (xx >= WW ? 2 * WW - 2 - xx : xx);
        hs[cl][r][cc] = g_h1[(((size_t)b * HID + ch0 + cl) * HH + yy) * WW + xx];
    }
    // 144 kernel taps over 128 threads: MUST be a strided loop (was the R2 bug)
    for (int idx = tid; idx < 144; idx += 128)
        ks[idx / 9][idx % 9] = Wb[(ch0 + idx / 9) * 9 + (idx % 9)];
    __syncthreads();

    int cl = tid >> 3, p = tid & 7;
    int ch = ch0 + cl;
    float inv = g2[ch] * rsqrtf(v2[ch] + EPSV);
    float sh  = b2[ch] - m2[ch] * inv;

    float r[8];
    #pragma unroll
    for (int q = 0; q < 8; q++) {
        float acc = 0.f;
        #pragma unroll
        for (int dy = 0; dy < 3; dy++)
            #pragma unroll
            for (int dx = 0; dx < 3; dx++)
                acc += hs[cl][p + dy][q + dx] * ks[cl][dy * 3 + dx];
        r[q] = fminf(fmaxf(acc * inv + sh, 0.f), 6.f);
    }
    float* dst = &g_h2[((size_t)(b * NPATCH + pid) * HID + ch) * 64 + p * 8];
    *(float4*)dst       = make_float4(r[0], r[1], r[2], r[3]);
    *(float4*)(dst + 4) = make_float4(r[4], r[5], r[6], r[7]);
}

// ---------------------------------------------------------------------------
// Stage 3: per-patch pointwise  out = x + bn3(W3 @ h2_patch)
// 1 CTA per patch, 128 threads. Thread tile 4co x 8px; k-chunks of 64.
// ---------------------------------------------------------------------------
__global__ __launch_bounds__(128) void k_stage3(
    const float* __restrict__ x,
    const float* __restrict__ g3, const float* __restrict__ b3,
    const float* __restrict__ m3, const float* __restrict__ v3,
    float* __restrict__ out)
{
    __shared__ float hs[64][64];    // [k][px]
    __shared__ float ws[64][65];    // [co][k]
    int blk = blockIdx.x;
    int b = blk >> 8, pid = blk & 255;
    int f = pid >> 4, g = pid & 15;
    int tid = threadIdx.x;
    int i = tid >> 3, j = tid & 7;
    int y0 = f * 8, x0 = g * 8;

    const float* Wb = g_wt + (size_t)(b * NPATCH + pid) * NP + P3OFF;
    const float* Hb = g_h2 + (size_t)(b * NPATCH + pid) * HID * 64;

    unsigned long long acc[4][4];
    #pragma unroll
    for (int a = 0; a < 4; a++)
        #pragma unroll
        for (int p2 = 0; p2 < 4; p2++) acc[a][p2] = 0ULL;

    for (int kt = 0; kt < 6; kt++) {
        __syncthreads();
        for (int idx = tid; idx < 1024; idx += 128) {       // 64k x 64px float4
            int k = idx >> 4, v4 = idx & 15;
            *(float4*)&hs[k][v4 * 4] = *(const float4*)&Hb[(kt * 64 + k) * 64 + v4 * 4];
        }
        for (int idx = tid; idx < 4096; idx += 128) {
            int co = idx >> 6, k = idx & 63;
            ws[co][k] = Wb[co * HID + kt * 64 + k];
        }
        __syncthreads();

        #pragma unroll 8
        for (int k = 0; k < 64; k++) {
            ulonglong2 xa = *(const ulonglong2*)&hs[k][j * 8];
            ulonglong2 xb = *(const ulonglong2*)&hs[k][j * 8 + 4];
            #pragma unroll
            for (int oo = 0; oo < 4; oo++) {
                unsigned long long w2 = pack2(ws[i * 4 + oo][k]);
                ffma2(acc[oo][0], xa.x, w2);
                ffma2(acc[oo][1], xa.y, w2);
                ffma2(acc[oo][2], xb.x, w2);
                ffma2(acc[oo][3], xb.y, w2);
            }
        }
    }

    #pragma unroll
    for (int oo = 0; oo < 4; oo++) {
        int co = i * 4 + oo;
        float inv = g3[co] * rsqrtf(v3[co] + EPSV);
        float sh  = b3[co] - m3[co] * inv;
        float r[8];
        #pragma unroll
        for (int p2 = 0; p2 < 4; p2++) unpack2(acc[oo][p2], r[p2 * 2], r[p2 * 2 + 1]);
        size_t base = (((size_t)b * COUT + co) * HH + y0 + j) * WW + x0;
        float4 xr0 = *(const float4*)&x[base];
        float4 xr1 = *(const float4*)&x[base + 4];
        float4 o0 = make_float4(xr0.x + (r[0] * inv + sh), xr0.y + (r[1] * inv + sh),
                                xr0.z + (r[2] * inv + sh), xr0.w + (r[3] * inv + sh));
        float4 o1 = make_float4(xr1.x + (r[4] * inv + sh), xr1.y + (r[5] * inv + sh),
                                xr1.z + (r[6] * inv + sh), xr1.w + (r[7] * inv + sh));
        *(float4*)&out[base]     = o0;
        *(float4*)&out[base + 4] = o1;
    }
}

// ---------------------------------------------------------------------------
extern "C" void kernel_launch(void* const* d_in, const int* in_sizes, int n_in,
                              void* d_out, int out_size) {
    const float* x  = (const float*)d_in[0];
    const float* w  = (const float*)d_in[1];
    const float* g1 = (const float*)d_in[2];
    const float* b1 = (const float*)d_in[3];
    const float* m1 = (const float*)d_in[4];
    const float* v1 = (const float*)d_in[5];
    const float* g2 = (const float*)d_in[6];
    const float* b2 = (const float*)d_in[7];
    const float* m2 = (const float*)d_in[8];
    const float* v2 = (const float*)d_in[9];
    const float* g3 = (const float*)d_in[10];
    const float* b3 = (const float*)d_in[11];
    const float* m3 = (const float*)d_in[12];
    const float* v3 = (const float*)d_in[13];
    float* out = (float*)d_out;

    dim3 tb(32, 8);
    dim3 tg(256 / 32, NP / 32, BB);   // (8, 1644, 4)
    k_transpose<<<tg, tb>>>(w);
    k_stage1<<<BB * NPATCH, 128>>>(x, g1, b1, m1, v1);
    k_stage2<<<dim3(BB * NPATCH, HID / 16), 128>>>(g2, b2, m2, v2);
    k_stage3<<<BB * NPATCH, 128>>>(x, g3, b3, m3, v3, out);
}

// round 4
// speedup vs baseline: 1.7822x; 1.0891x over previous
#include <cuda_runtime.h>

#define BB 4
#define CIN 64
#define HH 128
#define WW 128
#define HID 384
#define COUT 64
#define NPATCH 256          // 16 x 16
#define NP 52608            // params per patch
#define P2OFF 24576         // K2 offset (hidden*Cin)
#define P3OFF 28032         // W3 offset (+hidden*9)
#define EPSV 1e-5f

// scratch (static __device__ arrays; no runtime allocation)
__device__ float g_wt[(size_t)BB * NPATCH * NP];          // [b][patch][param] (K2 range unused)
__device__ float g_h1[(size_t)BB * HID * HH * WW];        // image layout ~100MB
__device__ float g_h2[(size_t)BB * NPATCH * HID * 64];    // patch-major ~100MB

// ---- packed f32x2 helpers (B300: 3-reg FFMA is half-rate; FFMA2 restores full rate)
__device__ __forceinline__ unsigned long long pack2(float v) {
    unsigned long long r;
    asm("mov.b64 %0, {%1, %1};" : "=l"(r) : "f"(v));
    return r;
}
__device__ __forceinline__ void ffma2(unsigned long long& d, unsigned long long a,
                                      unsigned long long b) {
    asm("fma.rn.f32x2 %0, %1, %2, %0;" : "+l"(d) : "l"(a), "l"(b));
}
__device__ __forceinline__ void unpack2(unsigned long long v, float& lo, float& hi) {
    asm("mov.b64 {%0, %1}, %2;" : "=f"(lo), "=f"(hi) : "l"(v));
}

// ---------------------------------------------------------------------------
// Transpose w [B][NP][256(fg)] -> g_wt [B][256(fg)][NP], skipping K2 range
// ---------------------------------------------------------------------------
__global__ __launch_bounds__(256) void k_transpose(const float* __restrict__ w) {
    __shared__ float tile[32][33];
    int b = blockIdx.z;
    size_t base = (size_t)b * NP * 256;
    int g0 = blockIdx.x * 32;   // fg dim (256 total)
    int y = blockIdx.y;         // 0..1535 (skips K2: tiles 768..875 of full range)
    int p0 = (y < 768) ? y * 32 : y * 32 + 3456;
    for (int i = threadIdx.y; i < 32; i += 8)
        tile[i][threadIdx.x] = w[base + (size_t)(p0 + i) * 256 + g0 + threadIdx.x];
    __syncthreads();
    for (int i = threadIdx.y; i < 32; i += 8)
        g_wt[base + (size_t)(g0 + i) * NP + p0 + threadIdx.x] = tile[threadIdx.x][i];
}

// ---------------------------------------------------------------------------
// Stage 1: per-patch pointwise  h1 = relu6(bn1(W1 @ x_patch))
// 1 CTA/patch, 128 threads, thread tile 4o x 8px, o-chunks of 64.
// ws layout [o][c] padded to 68 -> w loads are LDS.128 over 4 c.
// ---------------------------------------------------------------------------
__global__ __launch_bounds__(128) void k_stage1(
    const float* __restrict__ x,
    const float* __restrict__ g1, const float* __restrict__ b1,
    const float* __restrict__ m1, const float* __restrict__ v1)
{
    __shared__ float xs[64][64];    // [c][px]
    __shared__ float ws[64][68];    // [o][c] (+4 pad keeps rows 16B aligned, kills STS conflicts)
    int blk = blockIdx.x;
    int b = blk >> 8, pid = blk & 255;
    int f = pid >> 4, g = pid & 15;
    int tid = threadIdx.x;
    int i = tid >> 3, j = tid & 7;
    int y0 = f * 8, x0 = g * 8;

    for (int idx = tid; idx < 1024; idx += 128) {
        int c = idx >> 4, v4 = idx & 15;
        int p = v4 >> 1, q4 = (v4 & 1) * 4;
        *(float4*)&xs[c][v4 * 4] =
            *(const float4*)&x[(((size_t)b * CIN + c) * HH + y0 + p) * WW + x0 + q4];
    }
    const float* Wb = g_wt + (size_t)(b * NPATCH + pid) * NP;

    for (int ot = 0; ot < 6; ot++) {
        __syncthreads();
        // fill ws[o][c]: gmem rows (64 c) contiguous; float4 both sides
        for (int idx = tid; idx < 1024; idx += 128) {
            int o = idx >> 4, c4 = (idx & 15) * 4;
            *(float4*)&ws[o][c4] = *(const float4*)&Wb[(ot * 64 + o) * 64 + c4];
        }
        __syncthreads();

        unsigned long long acc[4][4];
        #pragma unroll
        for (int a = 0; a < 4; a++)
            #pragma unroll
            for (int p2 = 0; p2 < 4; p2++) acc[a][p2] = 0ULL;

        #pragma unroll 4
        for (int c4 = 0; c4 < 64; c4 += 4) {
            float4 wv[4];
            #pragma unroll
            for (int oo = 0; oo < 4; oo++)
                wv[oo] = *(const float4*)&ws[i * 4 + oo][c4];
            #pragma unroll
            for (int kk = 0; kk < 4; kk++) {
                int c = c4 + kk;
                ulonglong2 xa = *(const ulonglong2*)&xs[c][j * 8];
                ulonglong2 xb = *(const ulonglong2*)&xs[c][j * 8 + 4];
                #pragma unroll
                for (int oo = 0; oo < 4; oo++) {
                    unsigned long long w2 = pack2(((const float*)&wv[oo])[kk]);
                    ffma2(acc[oo][0], xa.x, w2);
                    ffma2(acc[oo][1], xa.y, w2);
                    ffma2(acc[oo][2], xb.x, w2);
                    ffma2(acc[oo][3], xb.y, w2);
                }
            }
        }

        #pragma unroll
        for (int oo = 0; oo < 4; oo++) {
            int o = ot * 64 + i * 4 + oo;
            float inv = g1[o] * rsqrtf(v1[o] + EPSV);
            float sh  = b1[o] - m1[o] * inv;
            float r[8];
            #pragma unroll
            for (int p2 = 0; p2 < 4; p2++) unpack2(acc[oo][p2], r[p2 * 2], r[p2 * 2 + 1]);
            #pragma unroll
            for (int q = 0; q < 8; q++)
                r[q] = fminf(fmaxf(r[q] * inv + sh, 0.f), 6.f);
            float* dst = &g_h1[(((size_t)b * HID + o) * HH + y0 + j) * WW + x0];
            *(float4*)dst       = make_float4(r[0], r[1], r[2], r[3]);
            *(float4*)(dst + 4) = make_float4(r[4], r[5], r[6], r[7]);
        }
    }
}

// ---------------------------------------------------------------------------
// Stage 2: per-patch depthwise 3x3 (reflect halo) + bn2 + relu6
// grid (1024 patches, 24 chgroups), 128 threads, 16 channels per CTA.
// K2 taps read straight from original w (L2-amortized across neighbor patches).
// ---------------------------------------------------------------------------
__global__ __launch_bounds__(128) void k_stage2(
    const float* __restrict__ w,
    const float* __restrict__ g2, const float* __restrict__ b2,
    const float* __restrict__ m2, const float* __restrict__ v2)
{
    __shared__ float hs[16][10][10];
    __shared__ float ks[16][9];
    int blk = blockIdx.x;
    int b = blk >> 8, pid = blk & 255;
    int f = pid >> 4, g = pid & 15;
    int ch0 = blockIdx.y * 16;
    int tid = threadIdx.x;
    int y0 = f * 8, x0 = g * 8;
    int fg = f * 16 + g;

    for (int idx = tid; idx < 1600; idx += 128) {
        int cl = idx / 100;
        int rem = idx - cl * 100;
        int r = rem / 10, cc = rem - r * 10;
        int yy = y0 + r - 1;
        int xx = x0 + cc - 1;
        yy = yy < 0 ? -yy : (yy >= HH ? 2 * HH - 2 - yy : yy);   // reflect
        xx = xx < 0 ? -xx : (xx >= WW ? 2 * WW - 2 - xx : xx);
        hs[cl][r][cc] = g_h1[(((size_t)b * HID + ch0 + cl) * HH + yy) * WW + xx];
    }
    for (int idx = tid; idx < 144; idx += 128) {
        int cl = idx / 9, t = idx - (idx / 9) * 9;
        ks[cl][t] = w[((size_t)b * NP + P2OFF + (ch0 + cl) * 9 + t) * 256 + fg];
    }
    __syncthreads();

    int cl = tid >> 3, p = tid & 7;
    int ch = ch0 + cl;
    float inv = g2[ch] * rsqrtf(v2[ch] + EPSV);
    float sh  = b2[ch] - m2[ch] * inv;

    float r[8];
    #pragma unroll
    for (int q = 0; q < 8; q++) {
        float acc = 0.f;
        #pragma unroll
        for (int dy = 0; dy < 3; dy++)
            #pragma unroll
            for (int dx = 0; dx < 3; dx++)
                acc += hs[cl][p + dy][q + dx] * ks[cl][dy * 3 + dx];
        r[q] = fminf(fmaxf(acc * inv + sh, 0.f), 6.f);
    }
    float* dst = &g_h2[((size_t)(b * NPATCH + pid) * HID + ch) * 64 + p * 8];
    *(float4*)dst       = make_float4(r[0], r[1], r[2], r[3]);
    *(float4*)(dst + 4) = make_float4(r[4], r[5], r[6], r[7]);
}

// ---------------------------------------------------------------------------
// Stage 3: per-patch pointwise  out = x + bn3(W3 @ h2_patch)
// Thread tile 4co x 8px; k-chunks of 64; ws layout [co][k] pad 68.
// ---------------------------------------------------------------------------
__global__ __launch_bounds__(128) void k_stage3(
    const float* __restrict__ x,
    const float* __restrict__ g3, const float* __restrict__ b3,
    const float* __restrict__ m3, const float* __restrict__ v3,
    float* __restrict__ out)
{
    __shared__ float hs[64][64];    // [k][px]
    __shared__ float ws[64][68];    // [co][k]
    int blk = blockIdx.x;
    int b = blk >> 8, pid = blk & 255;
    int f = pid >> 4, g = pid & 15;
    int tid = threadIdx.x;
    int i = tid >> 3, j = tid & 7;
    int y0 = f * 8, x0 = g * 8;

    const float* Wb = g_wt + (size_t)(b * NPATCH + pid) * NP + P3OFF;
    const float* Hb = g_h2 + (size_t)(b * NPATCH + pid) * HID * 64;

    unsigned long long acc[4][4];
    #pragma unroll
    for (int a = 0; a < 4; a++)
        #pragma unroll
        for (int p2 = 0; p2 < 4; p2++) acc[a][p2] = 0ULL;

    for (int kt = 0; kt < 6; kt++) {
        __syncthreads();
        for (int idx = tid; idx < 1024; idx += 128) {       // h2 chunk: contiguous copy
            int k = idx >> 4, v4 = idx & 15;
            *(float4*)&hs[k][v4 * 4] = *(const float4*)&Hb[(kt * 64 + k) * 64 + v4 * 4];
        }
        for (int idx = tid; idx < 1024; idx += 128) {       // ws[co][k]
            int co = idx >> 4, k4 = (idx & 15) * 4;
            *(float4*)&ws[co][k4] = *(const float4*)&Wb[co * HID + kt * 64 + k4];
        }
        __syncthreads();

        #pragma unroll 4
        for (int k4 = 0; k4 < 64; k4 += 4) {
            float4 wv[4];
            #pragma unroll
            for (int oo = 0; oo < 4; oo++)
                wv[oo] = *(const float4*)&ws[i * 4 + oo][k4];
            #pragma unroll
            for (int kk = 0; kk < 4; kk++) {
                int k = k4 + kk;
                ulonglong2 xa = *(const ulonglong2*)&hs[k][j * 8];
                ulonglong2 xb = *(const ulonglong2*)&hs[k][j * 8 + 4];
                #pragma unroll
                for (int oo = 0; oo < 4; oo++) {
                    unsigned long long w2 = pack2(((const float*)&wv[oo])[kk]);
                    ffma2(acc[oo][0], xa.x, w2);
                    ffma2(acc[oo][1], xa.y, w2);
                    ffma2(acc[oo][2], xb.x, w2);
                    ffma2(acc[oo][3], xb.y, w2);
                }
            }
        }
    }

    #pragma unroll
    for (int oo = 0; oo < 4; oo++) {
        int co = i * 4 + oo;
        float inv = g3[co] * rsqrtf(v3[co] + EPSV);
        float sh  = b3[co] - m3[co] * inv;
        float r[8];
        #pragma unroll
        for (int p2 = 0; p2 < 4; p2++) unpack2(acc[oo][p2], r[p2 * 2], r[p2 * 2 + 1]);
        size_t base = (((size_t)b * COUT + co) * HH + y0 + j) * WW + x0;
        float4 xr0 = *(const float4*)&x[base];
        float4 xr1 = *(const float4*)&x[base + 4];
        float4 o0 = make_float4(xr0.x + (r[0] * inv + sh), xr0.y + (r[1] * inv + sh),
                                xr0.z + (r[2] * inv + sh), xr0.w + (r[3] * inv + sh));
        float4 o1 = make_float4(xr1.x + (r[4] * inv + sh), xr1.y + (r[5] * inv + sh),
                                xr1.z + (r[6] * inv + sh), xr1.w + (r[7] * inv + sh));
        *(float4*)&out[base]     = o0;
        *(float4*)&out[base + 4] = o1;
    }
}

// ---------------------------------------------------------------------------
extern "C" void kernel_launch(void* const* d_in, const int* in_sizes, int n_in,
                              void* d_out, int out_size) {
    const float* x  = (const float*)d_in[0];
    const float* w  = (const float*)d_in[1];
    const float* g1 = (const float*)d_in[2];
    const float* b1 = (const float*)d_in[3];
    const float* m1 = (const float*)d_in[4];
    const float* v1 = (const float*)d_in[5];
    const float* g2 = (const float*)d_in[6];
    const float* b2 = (const float*)d_in[7];
    const float* m2 = (const float*)d_in[8];
    const float* v2 = (const float*)d_in[9];
    const float* g3 = (const float*)d_in[10];
    const float* b3 = (const float*)d_in[11];
    const float* m3 = (const float*)d_in[12];
    const float* v3 = (const float*)d_in[13];
    float* out = (float*)d_out;

    dim3 tb(32, 8);
    dim3 tg(256 / 32, 1536, BB);   // K2 param range skipped
    k_transpose<<<tg, tb>>>(w);
    k_stage1<<<BB * NPATCH, 128>>>(x, g1, b1, m1, v1);
    k_stage2<<<dim3(BB * NPATCH, HID / 16), 128>>>(w, g2, b2, m2, v2);
    k_stage3<<<BB * NPATCH, 128>>>(x, g3, b3, m3, v3, out);
}

// round 5
// speedup vs baseline: 1.9461x; 1.0919x over previous
#include <cuda_runtime.h>

#define BB 4
#define CIN 64
#define HH 128
#define WW 128
#define HID 384
#define COUT 64
#define NPATCH 256          // 16 x 16
#define NP 52608            // params per patch
#define P2OFF 24576         // K2 offset (hidden*Cin)
#define P3OFF 28032         // W3 offset (+hidden*9)
#define EPSV 1e-5f

// scratch (static __device__ arrays; no runtime allocation)
__device__ float g_wt[(size_t)BB * NPATCH * NP];          // [b][patch][param] (K2 range unused)
__device__ float g_h1[(size_t)BB * HID * HH * WW];        // image layout ~100MB
__device__ float g_h2[(size_t)BB * NPATCH * HID * 64];    // patch-major ~100MB

// ---- packed f32x2 helpers (B300: 3-reg FFMA is half-rate; FFMA2 restores full rate)
__device__ __forceinline__ unsigned long long pack2(float v) {
    unsigned long long r;
    asm("mov.b64 %0, {%1, %1};" : "=l"(r) : "f"(v));
    return r;
}
__device__ __forceinline__ void ffma2(unsigned long long& d, unsigned long long a,
                                      unsigned long long b) {
    asm("fma.rn.f32x2 %0, %1, %2, %0;" : "+l"(d) : "l"(a), "l"(b));
}
__device__ __forceinline__ void unpack2(unsigned long long v, float& lo, float& hi) {
    asm("mov.b64 {%0, %1}, %2;" : "=f"(lo), "=f"(hi) : "l"(v));
}

// ---------------------------------------------------------------------------
// Transpose w [B][NP][256(fg)] -> g_wt [B][256(fg)][NP], skipping K2 range
// ---------------------------------------------------------------------------
__global__ __launch_bounds__(256) void k_transpose(const float* __restrict__ w) {
    __shared__ float tile[32][33];
    int b = blockIdx.z;
    size_t base = (size_t)b * NP * 256;
    int g0 = blockIdx.x * 32;   // fg dim (256 total)
    int y = blockIdx.y;         // 0..1535 (skips K2 param range)
    int p0 = (y < 768) ? y * 32 : y * 32 + 3456;
    for (int i = threadIdx.y; i < 32; i += 8)
        tile[i][threadIdx.x] = w[base + (size_t)(p0 + i) * 256 + g0 + threadIdx.x];
    __syncthreads();
    for (int i = threadIdx.y; i < 32; i += 8)
        g_wt[base + (size_t)(g0 + i) * NP + p0 + threadIdx.x] = tile[threadIdx.x][i];
}

// ---------------------------------------------------------------------------
// Stage 1: per-patch pointwise  h1 = relu6(bn1(W1 @ x_patch))
// 1 CTA/patch, 128 threads, thread tile 8o x 8px, o-chunks of 128 (3 chunks).
// Thread (i=tid>>3, j=tid&7): o = chunk + i + oo*16 (oo=0..7), px row j.
// ws rows padded to 72 floats -> lane-adjacent rows hit disjoint 4-bank spans.
// ---------------------------------------------------------------------------
__global__ __launch_bounds__(128) void k_stage1(
    const float* __restrict__ x,
    const float* __restrict__ g1, const float* __restrict__ b1,
    const float* __restrict__ m1, const float* __restrict__ v1)
{
    extern __shared__ float smem[];
    float* xs = smem;              // [64][64]   16KB
    float* ws = smem + 4096;       // [128][72]  36.9KB
    int blk = blockIdx.x;
    int b = blk >> 8, pid = blk & 255;
    int f = pid >> 4, g = pid & 15;
    int tid = threadIdx.x;
    int i = tid >> 3, j = tid & 7;
    int y0 = f * 8, x0 = g * 8;

    for (int idx = tid; idx < 1024; idx += 128) {
        int c = idx >> 4, v4 = idx & 15;
        int p = v4 >> 1, q4 = (v4 & 1) * 4;
        *(float4*)&xs[c * 64 + v4 * 4] =
            *(const float4*)&x[(((size_t)b * CIN + c) * HH + y0 + p) * WW + x0 + q4];
    }
    const float* Wb = g_wt + (size_t)(b * NPATCH + pid) * NP;

    for (int ot = 0; ot < 3; ot++) {
        __syncthreads();
        for (int idx = tid; idx < 2048; idx += 128) {
            int o = idx >> 4, k4 = (idx & 15) * 4;
            *(float4*)&ws[o * 72 + k4] = *(const float4*)&Wb[(ot * 128 + o) * 64 + k4];
        }
        __syncthreads();

        unsigned long long acc[8][4];
        #pragma unroll
        for (int a = 0; a < 8; a++)
            #pragma unroll
            for (int p2 = 0; p2 < 4; p2++) acc[a][p2] = 0ULL;

        #pragma unroll 2
        for (int c4 = 0; c4 < 64; c4 += 4) {
            float4 wv[8];
            #pragma unroll
            for (int oo = 0; oo < 8; oo++)
                wv[oo] = *(const float4*)&ws[(i + oo * 16) * 72 + c4];
            #pragma unroll
            for (int kk = 0; kk < 4; kk++) {
                int c = c4 + kk;
                ulonglong2 xa = *(const ulonglong2*)&xs[c * 64 + j * 8];
                ulonglong2 xb = *(const ulonglong2*)&xs[c * 64 + j * 8 + 4];
                #pragma unroll
                for (int oo = 0; oo < 8; oo++) {
                    unsigned long long w2 = pack2(((const float*)&wv[oo])[kk]);
                    ffma2(acc[oo][0], xa.x, w2);
                    ffma2(acc[oo][1], xa.y, w2);
                    ffma2(acc[oo][2], xb.x, w2);
                    ffma2(acc[oo][3], xb.y, w2);
                }
            }
        }

        #pragma unroll
        for (int oo = 0; oo < 8; oo++) {
            int o = ot * 128 + i + oo * 16;
            float inv = g1[o] * rsqrtf(v1[o] + EPSV);
            float sh  = b1[o] - m1[o] * inv;
            float r[8];
            #pragma unroll
            for (int p2 = 0; p2 < 4; p2++) unpack2(acc[oo][p2], r[p2 * 2], r[p2 * 2 + 1]);
            #pragma unroll
            for (int q = 0; q < 8; q++)
                r[q] = fminf(fmaxf(r[q] * inv + sh, 0.f), 6.f);
            float* dst = &g_h1[(((size_t)b * HID + o) * HH + y0 + j) * WW + x0];
            *(float4*)dst       = make_float4(r[0], r[1], r[2], r[3]);
            *(float4*)(dst + 4) = make_float4(r[4], r[5], r[6], r[7]);
        }
    }
}

// ---------------------------------------------------------------------------
// Stage 2: per-patch depthwise 3x3 (reflect halo) + bn2 + relu6
// ---------------------------------------------------------------------------
__global__ __launch_bounds__(128) void k_stage2(
    const float* __restrict__ w,
    const float* __restrict__ g2, const float* __restrict__ b2,
    const float* __restrict__ m2, const float* __restrict__ v2)
{
    __shared__ float hs[16][10][10];
    __shared__ float ks[16][9];
    int blk = blockIdx.x;
    int b = blk >> 8, pid = blk & 255;
    int f = pid >> 4, g = pid & 15;
    int ch0 = blockIdx.y * 16;
    int tid = threadIdx.x;
    int y0 = f * 8, x0 = g * 8;
    int fg = f * 16 + g;

    for (int idx = tid; idx < 1600; idx += 128) {
        int cl = idx / 100;
        int rem = idx - cl * 100;
        int r = rem / 10, cc = rem - r * 10;
        int yy = y0 + r - 1;
        int xx = x0 + cc - 1;
        yy = yy < 0 ? -yy : (yy >= HH ? 2 * HH - 2 - yy : yy);   // reflect
        xx = xx < 0 ? -xx : (xx >= WW ? 2 * WW - 2 - xx : xx);
        hs[cl][r][cc] = g_h1[(((size_t)b * HID + ch0 + cl) * HH + yy) * WW + xx];
    }
    for (int idx = tid; idx < 144; idx += 128) {
        int cl = idx / 9, t = idx - (idx / 9) * 9;
        ks[cl][t] = w[((size_t)b * NP + P2OFF + (ch0 + cl) * 9 + t) * 256 + fg];
    }
    __syncthreads();

    int cl = tid >> 3, p = tid & 7;
    int ch = ch0 + cl;
    float inv = g2[ch] * rsqrtf(v2[ch] + EPSV);
    float sh  = b2[ch] - m2[ch] * inv;

    float r[8];
    #pragma unroll
    for (int q = 0; q < 8; q++) {
        float acc = 0.f;
        #pragma unroll
        for (int dy = 0; dy < 3; dy++)
            #pragma unroll
            for (int dx = 0; dx < 3; dx++)
                acc += hs[cl][p + dy][q + dx] * ks[cl][dy * 3 + dx];
        r[q] = fminf(fmaxf(acc * inv + sh, 0.f), 6.f);
    }
    float* dst = &g_h2[((size_t)(b * NPATCH + pid) * HID + ch) * 64 + p * 8];
    *(float4*)dst       = make_float4(r[0], r[1], r[2], r[3]);
    *(float4*)(dst + 4) = make_float4(r[4], r[5], r[6], r[7]);
}

// ---------------------------------------------------------------------------
// Stage 3: per-patch pointwise  out = x + bn3(W3 @ h2_patch)
// 2 patches per CTA (64co x 128px). Thread (i=tid>>4, j=tid&15): 8co x 8px.
// co = i + oo*8; patch_l = j>>3; row = j&7.
// ws: two 64x72 blocks, patch-B offset 4624 floats (bank shift 16) -> the 4
// lane-distinct addresses (i x patch) land on disjoint 4-bank spans.
// ---------------------------------------------------------------------------
#define S3_HROW 132
#define S3_WSP  4624   // patch-B offset in floats (64*72 + 16)
__global__ __launch_bounds__(128) void k_stage3(
    const float* __restrict__ x,
    const float* __restrict__ g3, const float* __restrict__ b3,
    const float* __restrict__ m3, const float* __restrict__ v3,
    float* __restrict__ out)
{
    extern __shared__ float smem[];
    float* hs = smem;                    // [64][132]  33.8KB
    float* ws = smem + 64 * S3_HROW;     // 2 x [64][72] + shift  36.9KB
    int blk = blockIdx.x;                // 0..511
    int b = blk >> 7, pp = blk & 127;
    int pid0 = pp * 2, pid1 = pp * 2 + 1;
    int tid = threadIdx.x;
    int i = tid >> 4, j = tid & 15;
    int patch_l = j >> 3;

    const float* Wb0 = g_wt + (size_t)(b * NPATCH + pid0) * NP + P3OFF;
    const float* Wb1 = g_wt + (size_t)(b * NPATCH + pid1) * NP + P3OFF;
    const float* Hb0 = g_h2 + (size_t)(b * NPATCH + pid0) * HID * 64;
    const float* Hb1 = g_h2 + (size_t)(b * NPATCH + pid1) * HID * 64;

    unsigned long long acc[8][4];
    #pragma unroll
    for (int a = 0; a < 8; a++)
        #pragma unroll
        for (int p2 = 0; p2 < 4; p2++) acc[a][p2] = 0ULL;

    for (int kt = 0; kt < 6; kt++) {
        __syncthreads();
        for (int idx = tid; idx < 2048; idx += 128) {       // hs: 64k x 128px
            int k = idx >> 5, v4 = idx & 31;
            int px4 = v4 * 4;
            const float* src = (px4 < 64) ? &Hb0[(kt * 64 + k) * 64 + px4]
                                          : &Hb1[(kt * 64 + k) * 64 + px4 - 64];
            *(float4*)&hs[k * S3_HROW + px4] = *(const float4*)src;
        }
        for (int idx = tid; idx < 2048; idx += 128) {       // ws: 2 x 64co x 64k
            int p = idx >> 10;
            int rem = idx & 1023;
            int co = rem >> 4, k4 = (rem & 15) * 4;
            const float* src = p ? &Wb1[co * HID + kt * 64 + k4]
                                 : &Wb0[co * HID + kt * 64 + k4];
            *(float4*)&ws[p * S3_WSP + co * 72 + k4] = *(const float4*)src;
        }
        __syncthreads();

        #pragma unroll 2
        for (int k4 = 0; k4 < 64; k4 += 4) {
            float4 wv[8];
            #pragma unroll
            for (int oo = 0; oo < 8; oo++)
                wv[oo] = *(const float4*)&ws[patch_l * S3_WSP + (i + oo * 8) * 72 + k4];
            #pragma unroll
            for (int kk = 0; kk < 4; kk++) {
                int k = k4 + kk;
                ulonglong2 xa = *(const ulonglong2*)&hs[k * S3_HROW + j * 8];
                ulonglong2 xb = *(const ulonglong2*)&hs[k * S3_HROW + j * 8 + 4];
                #pragma unroll
                for (int oo = 0; oo < 8; oo++) {
                    unsigned long long w2 = pack2(((const float*)&wv[oo])[kk]);
                    ffma2(acc[oo][0], xa.x, w2);
                    ffma2(acc[oo][1], xa.y, w2);
                    ffma2(acc[oo][2], xb.x, w2);
                    ffma2(acc[oo][3], xb.y, w2);
                }
            }
        }
    }

    int pid = patch_l ? pid1 : pid0;
    int f = pid >> 4, g = pid & 15;
    int y0 = f * 8, x0 = g * 8;
    int row = j & 7;
    #pragma unroll
    for (int oo = 0; oo < 8; oo++) {
        int co = i + oo * 8;
        float inv = g3[co] * rsqrtf(v3[co] + EPSV);
        float sh  = b3[co] - m3[co] * inv;
        float r[8];
        #pragma unroll
        for (int p2 = 0; p2 < 4; p2++) unpack2(acc[oo][p2], r[p2 * 2], r[p2 * 2 + 1]);
        size_t base = (((size_t)b * COUT + co) * HH + y0 + row) * WW + x0;
        float4 xr0 = *(const float4*)&x[base];
        float4 xr1 = *(const float4*)&x[base + 4];
        float4 o0 = make_float4(xr0.x + (r[0] * inv + sh), xr0.y + (r[1] * inv + sh),
                                xr0.z + (r[2] * inv + sh), xr0.w + (r[3] * inv + sh));
        float4 o1 = make_float4(xr1.x + (r[4] * inv + sh), xr1.y + (r[5] * inv + sh),
                                xr1.z + (r[6] * inv + sh), xr1.w + (r[7] * inv + sh));
        *(float4*)&out[base]     = o0;
        *(float4*)&out[base + 4] = o1;
    }
}

// ---------------------------------------------------------------------------
extern "C" void kernel_launch(void* const* d_in, const int* in_sizes, int n_in,
                              void* d_out, int out_size) {
    const float* x  = (const float*)d_in[0];
    const float* w  = (const float*)d_in[1];
    const float* g1 = (const float*)d_in[2];
    const float* b1 = (const float*)d_in[3];
    const float* m1 = (const float*)d_in[4];
    const float* v1 = (const float*)d_in[5];
    const float* g2 = (const float*)d_in[6];
    const float* b2 = (const float*)d_in[7];
    const float* m2 = (const float*)d_in[8];
    const float* v2 = (const float*)d_in[9];
    const float* g3 = (const float*)d_in[10];
    const float* b3 = (const float*)d_in[11];
    const float* m3 = (const float*)d_in[12];
    const float* v3 = (const float*)d_in[13];
    float* out = (float*)d_out;

    const int S1_SMEM = (4096 + 128 * 72) * 4;                 // 53248
    const int S3_SMEM = (64 * S3_HROW + S3_WSP + 64 * 72) * 4; // 70720
    static bool attr_set = false;
    if (!attr_set) {
        cudaFuncSetAttribute(k_stage1, cudaFuncAttributeMaxDynamicSharedMemorySize, S1_SMEM);
        cudaFuncSetAttribute(k_stage3, cudaFuncAttributeMaxDynamicSharedMemorySize, S3_SMEM);
        attr_set = true;
    }

    dim3 tb(32, 8);
    dim3 tg(256 / 32, 1536, BB);   // K2 param range skipped
    k_transpose<<<tg, tb>>>(w);
    k_stage1<<<BB * NPATCH, 128, S1_SMEM>>>(x, g1, b1, m1, v1);
    k_stage2<<<dim3(BB * NPATCH, HID / 16), 128>>>(w, g2, b2, m2, v2);
    k_stage3<<<BB * NPATCH / 2, 128, S3_SMEM>>>(x, g3, b3, m3, v3, out);
}

// round 6
// speedup vs baseline: 1.9644x; 1.0094x over previous
#include <cuda_runtime.h>

#define BB 4
#define CIN 64
#define HH 128
#define WW 128
#define HID 384
#define COUT 64
#define NPATCH 256          // 16 x 16
#define NP 52608            // params per patch
#define P2OFF 24576         // K2 offset (hidden*Cin)
#define P3OFF 28032         // W3 offset (+hidden*9)
#define EPSV 1e-5f

// scratch (static __device__ arrays; no runtime allocation)
__device__ float g_wt[(size_t)BB * NPATCH * NP];          // [b][patch][param] (K2 range unused)
__device__ float g_h1[(size_t)BB * HID * HH * WW];        // image layout ~100MB
__device__ float g_h2[(size_t)BB * NPATCH * HID * 64];    // patch-major ~100MB

// ---- packed f32x2 helpers
__device__ __forceinline__ unsigned long long pack2(float v) {
    unsigned long long r;
    asm("mov.b64 %0, {%1, %1};" : "=l"(r) : "f"(v));
    return r;
}
__device__ __forceinline__ void ffma2(unsigned long long& d, unsigned long long a,
                                      unsigned long long b) {
    asm("fma.rn.f32x2 %0, %1, %2, %0;" : "+l"(d) : "l"(a), "l"(b));
}
__device__ __forceinline__ void unpack2(unsigned long long v, float& lo, float& hi) {
    asm("mov.b64 {%0, %1}, %2;" : "=f"(lo), "=f"(hi) : "l"(v));
}

// activation column swizzle: px-group g (8 floats) lives at g*8 + (g>>2)*4
#define AROW 140
__device__ __forceinline__ int acol4(int v) {   // v = float4-index 0..31 (2 per group)
    int g = v >> 1;
    return g * 8 + (g >> 2) * 4 + (v & 1) * 4;
}

// w-tile: rows of 36 floats, patch1 shifted by WSP (bank shift 16)
#define WSP 2320   // 64*36 + 16

// ---------------------------------------------------------------------------
// Transpose w [B][NP][256(fg)] -> g_wt [B][256(fg)][NP], skipping K2 range
// ---------------------------------------------------------------------------
__global__ __launch_bounds__(256) void k_transpose(const float* __restrict__ w) {
    __shared__ float tile[32][33];
    int b = blockIdx.z;
    size_t base = (size_t)b * NP * 256;
    int g0 = blockIdx.x * 32;
    int y = blockIdx.y;
    int p0 = (y < 768) ? y * 32 : y * 32 + 3456;
    for (int i = threadIdx.y; i < 32; i += 8)
        tile[i][threadIdx.x] = w[base + (size_t)(p0 + i) * 256 + g0 + threadIdx.x];
    __syncthreads();
    for (int i = threadIdx.y; i < 32; i += 8)
        g_wt[base + (size_t)(g0 + i) * NP + p0 + threadIdx.x] = tile[threadIdx.x][i];
}

// ---------------------------------------------------------------------------
// Stage 1: 2 patches/CTA, 128 threads. D[64o x 128px] per o-chunk (6 chunks),
// c-chunks of 32. Thread (i=tid>>4, j=tid&15): 8o x 8px, o = base + i + 8*oo.
// ---------------------------------------------------------------------------
__global__ __launch_bounds__(128) void k_stage1(
    const float* __restrict__ x,
    const float* __restrict__ g1, const float* __restrict__ b1,
    const float* __restrict__ m1, const float* __restrict__ v1)
{
    extern __shared__ float smem[];
    float* xs = smem;                 // [64][140]  35.8KB
    float* ws = smem + 64 * AROW;     // 2 x [64][36] (+16 shift)  18.5KB
    int blk = blockIdx.x;             // 0..511
    int b = blk >> 7, pp = blk & 127;
    int pid0 = pp * 2, pid1 = pp * 2 + 1;
    int f = pid0 >> 4, gg0 = pid0 & 15;
    int y0 = f * 8, x0 = gg0 * 8;     // patch1 at x0+8 (same f row)
    int tid = threadIdx.x;
    int i = tid >> 4, j = tid & 15;
    int patch_l = j >> 3;
    int cb = j * 8 + (j >> 2) * 4;

    // load x for both patches: 64c x 128px
    for (int idx = tid; idx < 2048; idx += 128) {
        int c = idx >> 5, v = idx & 31;
        int pt = v >> 4, w4 = v & 15;
        int prow = w4 >> 1, q4 = (w4 & 1) * 4;
        *(float4*)&xs[c * AROW + acol4(v)] =
            *(const float4*)&x[(((size_t)b * CIN + c) * HH + y0 + prow) * WW + x0 + pt * 8 + q4];
    }
    const float* Wb0 = g_wt + (size_t)(b * NPATCH + pid0) * NP;
    const float* Wb1 = g_wt + (size_t)(b * NPATCH + pid1) * NP;

    for (int ot = 0; ot < 6; ot++) {
        unsigned long long acc[8][4];
        #pragma unroll
        for (int a = 0; a < 8; a++)
            #pragma unroll
            for (int p2 = 0; p2 < 4; p2++) acc[a][p2] = 0ULL;

        for (int ct = 0; ct < 2; ct++) {
            __syncthreads();
            for (int idx = tid; idx < 1024; idx += 128) {
                int p = idx >> 9, rem = idx & 511;
                int o = rem >> 3, c4 = (rem & 7) * 4;
                const float* src = p ? Wb1 : Wb0;
                *(float4*)&ws[p * WSP + o * 36 + c4] =
                    *(const float4*)&src[(ot * 64 + o) * 64 + ct * 32 + c4];
            }
            __syncthreads();

            #pragma unroll 2
            for (int c4 = 0; c4 < 32; c4 += 4) {
                float4 wv[8];
                #pragma unroll
                for (int oo = 0; oo < 8; oo++)
                    wv[oo] = *(const float4*)&ws[patch_l * WSP + (i + oo * 8) * 36 + c4];
                #pragma unroll
                for (int kk = 0; kk < 4; kk++) {
                    const float* xr = &xs[(ct * 32 + c4 + kk) * AROW + cb];
                    ulonglong2 xa = *(const ulonglong2*)xr;
                    ulonglong2 xb = *(const ulonglong2*)(xr + 4);
                    #pragma unroll
                    for (int oo = 0; oo < 8; oo++) {
                        unsigned long long w2 = pack2(((const float*)&wv[oo])[kk]);
                        ffma2(acc[oo][0], xa.x, w2);
                        ffma2(acc[oo][1], xa.y, w2);
                        ffma2(acc[oo][2], xb.x, w2);
                        ffma2(acc[oo][3], xb.y, w2);
                    }
                }
            }
        }

        int row = j & 7;
        #pragma unroll
        for (int oo = 0; oo < 8; oo++) {
            int o = ot * 64 + i + oo * 8;
            float inv = g1[o] * rsqrtf(v1[o] + EPSV);
            float sh  = b1[o] - m1[o] * inv;
            float r[8];
            #pragma unroll
            for (int p2 = 0; p2 < 4; p2++) unpack2(acc[oo][p2], r[p2 * 2], r[p2 * 2 + 1]);
            #pragma unroll
            for (int q = 0; q < 8; q++)
                r[q] = fminf(fmaxf(r[q] * inv + sh, 0.f), 6.f);
            float* dst = &g_h1[(((size_t)b * HID + o) * HH + y0 + row) * WW + x0 + patch_l * 8];
            *(float4*)dst       = make_float4(r[0], r[1], r[2], r[3]);
            *(float4*)(dst + 4) = make_float4(r[4], r[5], r[6], r[7]);
        }
    }
}

// ---------------------------------------------------------------------------
// Stage 2: per-patch depthwise 3x3 (reflect halo) + bn2 + relu6
// ---------------------------------------------------------------------------
__global__ __launch_bounds__(128) void k_stage2(
    const float* __restrict__ w,
    const float* __restrict__ g2, const float* __restrict__ b2,
    const float* __restrict__ m2, const float* __restrict__ v2)
{
    __shared__ float hs[16][10][10];
    __shared__ float ks[16][9];
    int blk = blockIdx.x;
    int b = blk >> 8, pid = blk & 255;
    int f = pid >> 4, g = pid & 15;
    int ch0 = blockIdx.y * 16;
    int tid = threadIdx.x;
    int y0 = f * 8, x0 = g * 8;
    int fg = f * 16 + g;

    for (int idx = tid; idx < 1600; idx += 128) {
        int cl = idx / 100;
        int rem = idx - cl * 100;
        int r = rem / 10, cc = rem - r * 10;
        int yy = y0 + r - 1;
        int xx = x0 + cc - 1;
        yy = yy < 0 ? -yy : (yy >= HH ? 2 * HH - 2 - yy : yy);
        xx = xx < 0 ? -xx : (xx >= WW ? 2 * WW - 2 - xx : xx);
        hs[cl][r][cc] = g_h1[(((size_t)b * HID + ch0 + cl) * HH + yy) * WW + xx];
    }
    for (int idx = tid; idx < 144; idx += 128) {
        int cl = idx / 9, t = idx - (idx / 9) * 9;
        ks[cl][t] = w[((size_t)b * NP + P2OFF + (ch0 + cl) * 9 + t) * 256 + fg];
    }
    __syncthreads();

    int cl = tid >> 3, p = tid & 7;
    int ch = ch0 + cl;
    float inv = g2[ch] * rsqrtf(v2[ch] + EPSV);
    float sh  = b2[ch] - m2[ch] * inv;

    float r[8];
    #pragma unroll
    for (int q = 0; q < 8; q++) {
        float acc = 0.f;
        #pragma unroll
        for (int dy = 0; dy < 3; dy++)
            #pragma unroll
            for (int dx = 0; dx < 3; dx++)
                acc += hs[cl][p + dy][q + dx] * ks[cl][dy * 3 + dx];
        r[q] = fminf(fmaxf(acc * inv + sh, 0.f), 6.f);
    }
    float* dst = &g_h2[((size_t)(b * NPATCH + pid) * HID + ch) * 64 + p * 8];
    *(float4*)dst       = make_float4(r[0], r[1], r[2], r[3]);
    *(float4*)(dst + 4) = make_float4(r[4], r[5], r[6], r[7]);
}

// ---------------------------------------------------------------------------
// Stage 3: 2 patches/CTA, k-chunks of 32 (12 chunks). Thread 8co x 8px.
// smem 36.4KB -> 6 CTAs/SM.
// ---------------------------------------------------------------------------
__global__ __launch_bounds__(128) void k_stage3(
    const float* __restrict__ x,
    const float* __restrict__ g3, const float* __restrict__ b3,
    const float* __restrict__ m3, const float* __restrict__ v3,
    float* __restrict__ out)
{
    extern __shared__ float smem[];
    float* hs = smem;                 // [32][140]  17.9KB
    float* ws = smem + 32 * AROW;     // 2 x [64][36] (+16 shift)  18.5KB
    int blk = blockIdx.x;             // 0..511
    int b = blk >> 7, pp = blk & 127;
    int pid0 = pp * 2, pid1 = pp * 2 + 1;
    int f = pid0 >> 4, gg0 = pid0 & 15;
    int y0 = f * 8, x0 = gg0 * 8;
    int tid = threadIdx.x;
    int i = tid >> 4, j = tid & 15;
    int patch_l = j >> 3;
    int cb = j * 8 + (j >> 2) * 4;

    const float* Wb0 = g_wt + (size_t)(b * NPATCH + pid0) * NP + P3OFF;
    const float* Wb1 = g_wt + (size_t)(b * NPATCH + pid1) * NP + P3OFF;
    const float* Hb0 = g_h2 + (size_t)(b * NPATCH + pid0) * HID * 64;
    const float* Hb1 = g_h2 + (size_t)(b * NPATCH + pid1) * HID * 64;

    unsigned long long acc[8][4];
    #pragma unroll
    for (int a = 0; a < 8; a++)
        #pragma unroll
        for (int p2 = 0; p2 < 4; p2++) acc[a][p2] = 0ULL;

    for (int kt = 0; kt < 12; kt++) {
        __syncthreads();
        for (int idx = tid; idx < 1024; idx += 128) {       // hs: 32k x 128px
            int k = idx >> 5, v = idx & 31;
            int pt = v >> 4, w4 = v & 15;
            const float* src = pt ? Hb1 : Hb0;
            *(float4*)&hs[k * AROW + acol4(v)] =
                *(const float4*)&src[(kt * 32 + k) * 64 + w4 * 4];
        }
        for (int idx = tid; idx < 1024; idx += 128) {       // ws: 2 x 64co x 32k
            int p = idx >> 9, rem = idx & 511;
            int co = rem >> 3, c4 = (rem & 7) * 4;
            const float* src = p ? Wb1 : Wb0;
            *(float4*)&ws[p * WSP + co * 36 + c4] =
                *(const float4*)&src[co * HID + kt * 32 + c4];
        }
        __syncthreads();

        #pragma unroll 2
        for (int c4 = 0; c4 < 32; c4 += 4) {
            float4 wv[8];
            #pragma unroll
            for (int oo = 0; oo < 8; oo++)
                wv[oo] = *(const float4*)&ws[patch_l * WSP + (i + oo * 8) * 36 + c4];
            #pragma unroll
            for (int kk = 0; kk < 4; kk++) {
                const float* xr = &hs[(c4 + kk) * AROW + cb];
                ulonglong2 xa = *(const ulonglong2*)xr;
                ulonglong2 xb = *(const ulonglong2*)(xr + 4);
                #pragma unroll
                for (int oo = 0; oo < 8; oo++) {
                    unsigned long long w2 = pack2(((const float*)&wv[oo])[kk]);
                    ffma2(acc[oo][0], xa.x, w2);
                    ffma2(acc[oo][1], xa.y, w2);
                    ffma2(acc[oo][2], xb.x, w2);
                    ffma2(acc[oo][3], xb.y, w2);
                }
            }
        }
    }

    int row = j & 7;
    #pragma unroll
    for (int oo = 0; oo < 8; oo++) {
        int co = i + oo * 8;
        float inv = g3[co] * rsqrtf(v3[co] + EPSV);
        float sh  = b3[co] - m3[co] * inv;
        float r[8];
        #pragma unroll
        for (int p2 = 0; p2 < 4; p2++) unpack2(acc[oo][p2], r[p2 * 2], r[p2 * 2 + 1]);
        size_t base = (((size_t)b * COUT + co) * HH + y0 + row) * WW + x0 + patch_l * 8;
        float4 xr0 = *(const float4*)&x[base];
        float4 xr1 = *(const float4*)&x[base + 4];
        float4 o0 = make_float4(xr0.x + (r[0] * inv + sh), xr0.y + (r[1] * inv + sh),
                                xr0.z + (r[2] * inv + sh), xr0.w + (r[3] * inv + sh));
        float4 o1 = make_float4(xr1.x + (r[4] * inv + sh), xr1.y + (r[5] * inv + sh),
                                xr1.z + (r[6] * inv + sh), xr1.w + (r[7] * inv + sh));
        *(float4*)&out[base]     = o0;
        *(float4*)&out[base + 4] = o1;
    }
}

// ---------------------------------------------------------------------------
extern "C" void kernel_launch(void* const* d_in, const int* in_sizes, int n_in,
                              void* d_out, int out_size) {
    const float* x  = (const float*)d_in[0];
    const float* w  = (const float*)d_in[1];
    const float* g1 = (const float*)d_in[2];
    const float* b1 = (const float*)d_in[3];
    const float* m1 = (const float*)d_in[4];
    const float* v1 = (const float*)d_in[5];
    const float* g2 = (const float*)d_in[6];
    const float* b2 = (const float*)d_in[7];
    const float* m2 = (const float*)d_in[8];
    const float* v2 = (const float*)d_in[9];
    const float* g3 = (const float*)d_in[10];
    const float* b3 = (const float*)d_in[11];
    const float* m3 = (const float*)d_in[12];
    const float* v3 = (const float*)d_in[13];
    float* out = (float*)d_out;

    const int S1_SMEM = (64 * AROW + WSP + 64 * 36) * 4;   // 54336
    const int S3_SMEM = (32 * AROW + WSP + 64 * 36) * 4;   // 36416
    cudaFuncSetAttribute(k_stage1, cudaFuncAttributeMaxDynamicSharedMemorySize, S1_SMEM);
    cudaFuncSetAttribute(k_stage3, cudaFuncAttributeMaxDynamicSharedMemorySize, S3_SMEM);

    dim3 tb(32, 8);
    dim3 tg(256 / 32, 1536, BB);   // K2 param range skipped
    k_transpose<<<tg, tb>>>(w);
    k_stage1<<<BB * NPATCH / 2, 128, S1_SMEM>>>(x, g1, b1, m1, v1);
    k_stage2<<<dim3(BB * NPATCH, HID / 16), 128>>>(w, g2, b2, m2, v2);
    k_stage3<<<BB * NPATCH / 2, 128, S3_SMEM>>>(x, g3, b3, m3, v3, out);
}

// round 7
// speedup vs baseline: 2.0540x; 1.0456x over previous
#include <cuda_runtime.h>

#define BB 4
#define CIN 64
#define HH 128
#define WW 128
#define HID 384
#define COUT 64
#define NPATCH 256          // 16 x 16
#define NP 52608            // params per patch
#define P2OFF 24576         // K2 offset (hidden*Cin)
#define P3OFF 28032         // W3 offset (+hidden*9)
#define EPSV 1e-5f

// scratch (static __device__ arrays; no runtime allocation)
__device__ float g_wt[(size_t)BB * NPATCH * NP];          // [b][patch][param] (K2 range unused)
__device__ float g_h1[(size_t)BB * HID * HH * WW];        // image layout ~100MB
__device__ float g_h2[(size_t)BB * NPATCH * HID * 64];    // patch-major ~100MB

// ---- packed f32x2 helpers
__device__ __forceinline__ unsigned long long pack2(float v) {
    unsigned long long r;
    asm("mov.b64 %0, {%1, %1};" : "=l"(r) : "f"(v));
    return r;
}
__device__ __forceinline__ void ffma2(unsigned long long& d, unsigned long long a,
                                      unsigned long long b) {
    asm("fma.rn.f32x2 %0, %1, %2, %0;" : "+l"(d) : "l"(a), "l"(b));
}
__device__ __forceinline__ void unpack2(unsigned long long v, float& lo, float& hi) {
    asm("mov.b64 {%0, %1}, %2;" : "=f"(lo), "=f"(hi) : "l"(v));
}

// activation column swizzle: px-group g (8 floats) lives at g*8 + (g>>2)*4
#define AROW 140
__device__ __forceinline__ int acol4(int v) {   // v = float4-index 0..31 (2 per group)
    int g = v >> 1;
    return g * 8 + (g >> 2) * 4 + (v & 1) * 4;
}

// w-tile: rows of 36 floats, patch1 shifted by WSP (bank shift 16)
#define WSP 2320   // 64*36 + 16

// ---------------------------------------------------------------------------
// Transpose w [B][NP][256(fg)] -> g_wt [B][256(fg)][NP], skipping K2 range
// ---------------------------------------------------------------------------
__global__ __launch_bounds__(256) void k_transpose(const float* __restrict__ w) {
    __shared__ float tile[32][33];
    int b = blockIdx.z;
    size_t base = (size_t)b * NP * 256;
    int g0 = blockIdx.x * 32;
    int y = blockIdx.y;
    int p0 = (y < 768) ? y * 32 : y * 32 + 3456;
    for (int i = threadIdx.y; i < 32; i += 8)
        tile[i][threadIdx.x] = w[base + (size_t)(p0 + i) * 256 + g0 + threadIdx.x];
    __syncthreads();
    for (int i = threadIdx.y; i < 32; i += 8)
        g_wt[base + (size_t)(g0 + i) * NP + p0 + threadIdx.x] = tile[threadIdx.x][i];
}

// ---------------------------------------------------------------------------
// Stage 1: 2 patches/CTA, 128 threads. D[64o x 128px] per o-chunk (6 chunks),
// c-chunks of 32. Thread (i=tid>>4, j=tid&15): 8o x 8px, o = base + i + 8*oo.
// launch_bounds(128,4): <=128 regs -> 4 CTAs/SM -> grid 512 in ONE wave.
// ---------------------------------------------------------------------------
__global__ __launch_bounds__(128, 4) void k_stage1(
    const float* __restrict__ x,
    const float* __restrict__ g1, const float* __restrict__ b1,
    const float* __restrict__ m1, const float* __restrict__ v1)
{
    extern __shared__ float smem[];
    float* xs = smem;                 // [64][140]  35.8KB
    float* ws = smem + 64 * AROW;     // 2 x [64][36] (+16 shift)  18.5KB
    int blk = blockIdx.x;             // 0..511
    int b = blk >> 7, pp = blk & 127;
    int pid0 = pp * 2, pid1 = pp * 2 + 1;
    int f = pid0 >> 4, gg0 = pid0 & 15;
    int y0 = f * 8, x0 = gg0 * 8;     // patch1 at x0+8 (same f row)
    int tid = threadIdx.x;
    int i = tid >> 4, j = tid & 15;
    int patch_l = j >> 3;
    int cb = j * 8 + (j >> 2) * 4;

    // load x for both patches: 64c x 128px
    for (int idx = tid; idx < 2048; idx += 128) {
        int c = idx >> 5, v = idx & 31;
        int pt = v >> 4, w4 = v & 15;
        int prow = w4 >> 1, q4 = (w4 & 1) * 4;
        *(float4*)&xs[c * AROW + acol4(v)] =
            *(const float4*)&x[(((size_t)b * CIN + c) * HH + y0 + prow) * WW + x0 + pt * 8 + q4];
    }
    const float* Wb0 = g_wt + (size_t)(b * NPATCH + pid0) * NP;
    const float* Wb1 = g_wt + (size_t)(b * NPATCH + pid1) * NP;

    for (int ot = 0; ot < 6; ot++) {
        unsigned long long acc[8][4];
        #pragma unroll
        for (int a = 0; a < 8; a++)
            #pragma unroll
            for (int p2 = 0; p2 < 4; p2++) acc[a][p2] = 0ULL;

        for (int ct = 0; ct < 2; ct++) {
            __syncthreads();
            for (int idx = tid; idx < 1024; idx += 128) {
                int p = idx >> 9, rem = idx & 511;
                int o = rem >> 3, c4 = (rem & 7) * 4;
                const float* src = p ? Wb1 : Wb0;
                *(float4*)&ws[p * WSP + o * 36 + c4] =
                    *(const float4*)&src[(ot * 64 + o) * 64 + ct * 32 + c4];
            }
            __syncthreads();

            #pragma unroll 2
            for (int c4 = 0; c4 < 32; c4 += 4) {
                float4 wv[8];
                #pragma unroll
                for (int oo = 0; oo < 8; oo++)
                    wv[oo] = *(const float4*)&ws[patch_l * WSP + (i + oo * 8) * 36 + c4];
                #pragma unroll
                for (int kk = 0; kk < 4; kk++) {
                    const float* xr = &xs[(ct * 32 + c4 + kk) * AROW + cb];
                    ulonglong2 xa = *(const ulonglong2*)xr;
                    ulonglong2 xb = *(const ulonglong2*)(xr + 4);
                    #pragma unroll
                    for (int oo = 0; oo < 8; oo++) {
                        unsigned long long w2 = pack2(((const float*)&wv[oo])[kk]);
                        ffma2(acc[oo][0], xa.x, w2);
                        ffma2(acc[oo][1], xa.y, w2);
                        ffma2(acc[oo][2], xb.x, w2);
                        ffma2(acc[oo][3], xb.y, w2);
                    }
                }
            }
        }

        int row = j & 7;
        #pragma unroll
        for (int oo = 0; oo < 8; oo++) {
            int o = ot * 64 + i + oo * 8;
            float inv = g1[o] * rsqrtf(v1[o] + EPSV);
            float sh  = b1[o] - m1[o] * inv;
            float r[8];
            #pragma unroll
            for (int p2 = 0; p2 < 4; p2++) unpack2(acc[oo][p2], r[p2 * 2], r[p2 * 2 + 1]);
            #pragma unroll
            for (int q = 0; q < 8; q++)
                r[q] = fminf(fmaxf(r[q] * inv + sh, 0.f), 6.f);
            float* dst = &g_h1[(((size_t)b * HID + o) * HH + y0 + row) * WW + x0 + patch_l * 8];
            *(float4*)dst       = make_float4(r[0], r[1], r[2], r[3]);
            *(float4*)(dst + 4) = make_float4(r[4], r[5], r[6], r[7]);
        }
    }
}

// ---------------------------------------------------------------------------
// Stage 2: per-patch depthwise 3x3 (reflect halo) + bn2 + relu6
// ---------------------------------------------------------------------------
__global__ __launch_bounds__(128) void k_stage2(
    const float* __restrict__ w,
    const float* __restrict__ g2, const float* __restrict__ b2,
    const float* __restrict__ m2, const float* __restrict__ v2)
{
    __shared__ float hs[16][10][10];
    __shared__ float ks[16][9];
    int blk = blockIdx.x;
    int b = blk >> 8, pid = blk & 255;
    int f = pid >> 4, g = pid & 15;
    int ch0 = blockIdx.y * 16;
    int tid = threadIdx.x;
    int y0 = f * 8, x0 = g * 8;
    int fg = f * 16 + g;

    for (int idx = tid; idx < 1600; idx += 128) {
        int cl = idx / 100;
        int rem = idx - cl * 100;
        int r = rem / 10, cc = rem - r * 10;
        int yy = y0 + r - 1;
        int xx = x0 + cc - 1;
        yy = yy < 0 ? -yy : (yy >= HH ? 2 * HH - 2 - yy : yy);
        xx = xx < 0 ? -xx : (xx >= WW ? 2 * WW - 2 - xx : xx);
        hs[cl][r][cc] = g_h1[(((size_t)b * HID + ch0 + cl) * HH + yy) * WW + xx];
    }
    for (int idx = tid; idx < 144; idx += 128) {
        int cl = idx / 9, t = idx - (idx / 9) * 9;
        ks[cl][t] = w[((size_t)b * NP + P2OFF + (ch0 + cl) * 9 + t) * 256 + fg];
    }
    __syncthreads();

    int cl = tid >> 3, p = tid & 7;
    int ch = ch0 + cl;
    float inv = g2[ch] * rsqrtf(v2[ch] + EPSV);
    float sh  = b2[ch] - m2[ch] * inv;

    float r[8];
    #pragma unroll
    for (int q = 0; q < 8; q++) {
        float acc = 0.f;
        #pragma unroll
        for (int dy = 0; dy < 3; dy++)
            #pragma unroll
            for (int dx = 0; dx < 3; dx++)
                acc += hs[cl][p + dy][q + dx] * ks[cl][dy * 3 + dx];
        r[q] = fminf(fmaxf(acc * inv + sh, 0.f), 6.f);
    }
    float* dst = &g_h2[((size_t)(b * NPATCH + pid) * HID + ch) * 64 + p * 8];
    *(float4*)dst       = make_float4(r[0], r[1], r[2], r[3]);
    *(float4*)(dst + 4) = make_float4(r[4], r[5], r[6], r[7]);
}

// ---------------------------------------------------------------------------
// Stage 3: 2 patches/CTA, k-chunks of 32 (12 chunks). Thread 8co x 8px.
// launch_bounds(128,4): <=128 regs -> 4 CTAs/SM -> single wave.
// ---------------------------------------------------------------------------
__global__ __launch_bounds__(128, 4) void k_stage3(
    const float* __restrict__ x,
    const float* __restrict__ g3, const float* __restrict__ b3,
    const float* __restrict__ m3, const float* __restrict__ v3,
    float* __restrict__ out)
{
    extern __shared__ float smem[];
    float* hs = smem;                 // [32][140]  17.9KB
    float* ws = smem + 32 * AROW;     // 2 x [64][36] (+16 shift)  18.5KB
    int blk = blockIdx.x;             // 0..511
    int b = blk >> 7, pp = blk & 127;
    int pid0 = pp * 2, pid1 = pp * 2 + 1;
    int f = pid0 >> 4, gg0 = pid0 & 15;
    int y0 = f * 8, x0 = gg0 * 8;
    int tid = threadIdx.x;
    int i = tid >> 4, j = tid & 15;
    int patch_l = j >> 3;
    int cb = j * 8 + (j >> 2) * 4;

    const float* Wb0 = g_wt + (size_t)(b * NPATCH + pid0) * NP + P3OFF;
    const float* Wb1 = g_wt + (size_t)(b * NPATCH + pid1) * NP + P3OFF;
    const float* Hb0 = g_h2 + (size_t)(b * NPATCH + pid0) * HID * 64;
    const float* Hb1 = g_h2 + (size_t)(b * NPATCH + pid1) * HID * 64;

    unsigned long long acc[8][4];
    #pragma unroll
    for (int a = 0; a < 8; a++)
        #pragma unroll
        for (int p2 = 0; p2 < 4; p2++) acc[a][p2] = 0ULL;

    for (int kt = 0; kt < 12; kt++) {
        __syncthreads();
        for (int idx = tid; idx < 1024; idx += 128) {       // hs: 32k x 128px
            int k = idx >> 5, v = idx & 31;
            int pt = v >> 4, w4 = v & 15;
            const float* src = pt ? Hb1 : Hb0;
            *(float4*)&hs[k * AROW + acol4(v)] =
                *(const float4*)&src[(kt * 32 + k) * 64 + w4 * 4];
        }
        for (int idx = tid; idx < 1024; idx += 128) {       // ws: 2 x 64co x 32k
            int p = idx >> 9, rem = idx & 511;
            int co = rem >> 3, c4 = (rem & 7) * 4;
            const float* src = p ? Wb1 : Wb0;
            *(float4*)&ws[p * WSP + co * 36 + c4] =
                *(const float4*)&src[co * HID + kt * 32 + c4];
        }
        __syncthreads();

        #pragma unroll 2
        for (int c4 = 0; c4 < 32; c4 += 4) {
            float4 wv[8];
            #pragma unroll
            for (int oo = 0; oo < 8; oo++)
                wv[oo] = *(const float4*)&ws[patch_l * WSP + (i + oo * 8) * 36 + c4];
            #pragma unroll
            for (int kk = 0; kk < 4; kk++) {
                const float* xr = &hs[(c4 + kk) * AROW + cb];
                ulonglong2 xa = *(const ulonglong2*)xr;
                ulonglong2 xb = *(const ulonglong2*)(xr + 4);
                #pragma unroll
                for (int oo = 0; oo < 8; oo++) {
                    unsigned long long w2 = pack2(((const float*)&wv[oo])[kk]);
                    ffma2(acc[oo][0], xa.x, w2);
                    ffma2(acc[oo][1], xa.y, w2);
                    ffma2(acc[oo][2], xb.x, w2);
                    ffma2(acc[oo][3], xb.y, w2);
                }
            }
        }
    }

    int row = j & 7;
    #pragma unroll
    for (int oo = 0; oo < 8; oo++) {
        int co = i + oo * 8;
        float inv = g3[co] * rsqrtf(v3[co] + EPSV);
        float sh  = b3[co] - m3[co] * inv;
        float r[8];
        #pragma unroll
        for (int p2 = 0; p2 < 4; p2++) unpack2(acc[oo][p2], r[p2 * 2], r[p2 * 2 + 1]);
        size_t base = (((size_t)b * COUT + co) * HH + y0 + row) * WW + x0 + patch_l * 8;
        float4 xr0 = *(const float4*)&x[base];
        float4 xr1 = *(const float4*)&x[base + 4];
        float4 o0 = make_float4(xr0.x + (r[0] * inv + sh), xr0.y + (r[1] * inv + sh),
                                xr0.z + (r[2] * inv + sh), xr0.w + (r[3] * inv + sh));
        float4 o1 = make_float4(xr1.x + (r[4] * inv + sh), xr1.y + (r[5] * inv + sh),
                                xr1.z + (r[6] * inv + sh), xr1.w + (r[7] * inv + sh));
        *(float4*)&out[base]     = o0;
        *(float4*)&out[base + 4] = o1;
    }
}

// ---------------------------------------------------------------------------
extern "C" void kernel_launch(void* const* d_in, const int* in_sizes, int n_in,
                              void* d_out, int out_size) {
    const float* x  = (const float*)d_in[0];
    const float* w  = (const float*)d_in[1];
    const float* g1 = (const float*)d_in[2];
    const float* b1 = (const float*)d_in[3];
    const float* m1 = (const float*)d_in[4];
    const float* v1 = (const float*)d_in[5];
    const float* g2 = (const float*)d_in[6];
    const float* b2 = (const float*)d_in[7];
    const float* m2 = (const float*)d_in[8];
    const float* v2 = (const float*)d_in[9];
    const float* g3 = (const float*)d_in[10];
    const float* b3 = (const float*)d_in[11];
    const float* m3 = (const float*)d_in[12];
    const float* v3 = (const float*)d_in[13];
    float* out = (float*)d_out;

    const int S1_SMEM = (64 * AROW + WSP + 64 * 36) * 4;   // 54336
    const int S3_SMEM = (32 * AROW + WSP + 64 * 36) * 4;   // 36416
    cudaFuncSetAttribute(k_stage1, cudaFuncAttributeMaxDynamicSharedMemorySize, S1_SMEM);
    cudaFuncSetAttribute(k_stage3, cudaFuncAttributeMaxDynamicSharedMemorySize, S3_SMEM);

    dim3 tb(32, 8);
    dim3 tg(256 / 32, 1536, BB);   // K2 param range skipped
    k_transpose<<<tg, tb>>>(w);
    k_stage1<<<BB * NPATCH / 2, 128, S1_SMEM>>>(x, g1, b1, m1, v1);
    k_stage2<<<dim3(BB * NPATCH, HID / 16), 128>>>(w, g2, b2, m2, v2);
    k_stage3<<<BB * NPATCH / 2, 128, S3_SMEM>>>(x, g3, b3, m3, v3, out);
}

// round 8
// speedup vs baseline: 2.1654x; 1.0542x over previous
#include <cuda_runtime.h>
#include <cstdint>

#define BB 4
#define CIN 64
#define HH 128
#define WW 128
#define HID 384
#define COUT 64
#define NPATCH 256          // 16 x 16
#define NP 52608            // params per patch
#define P2OFF 24576         // K2 offset (hidden*Cin)
#define P3OFF 28032         // W3 offset (+hidden*9)
#define EPSV 1e-5f

// scratch (static __device__ arrays; no runtime allocation)
__device__ float g_wt[(size_t)BB * NPATCH * NP];          // [b][patch][param] (K2 range unused)
__device__ float g_h1[(size_t)BB * HID * HH * WW];        // image layout ~100MB
__device__ float g_h2[(size_t)BB * NPATCH * HID * 64];    // patch-major ~100MB

// ---- packed f32x2 helpers
__device__ __forceinline__ unsigned long long pack2(float v) {
    unsigned long long r;
    asm("mov.b64 %0, {%1, %1};" : "=l"(r) : "f"(v));
    return r;
}
__device__ __forceinline__ void ffma2(unsigned long long& d, unsigned long long a,
                                      unsigned long long b) {
    asm("fma.rn.f32x2 %0, %1, %2, %0;" : "+l"(d) : "l"(a), "l"(b));
}
__device__ __forceinline__ void unpack2(unsigned long long v, float& lo, float& hi) {
    asm("mov.b64 {%0, %1}, %2;" : "=f"(lo), "=f"(hi) : "l"(v));
}

// ---- cp.async helpers
__device__ __forceinline__ void cp16(uint32_t dst_smem, const void* src) {
    asm volatile("cp.async.cg.shared.global [%0], [%1], 16;"
                 :: "r"(dst_smem), "l"(src) : "memory");
}
#define CP_COMMIT() asm volatile("cp.async.commit_group;" ::: "memory")
#define CP_WAIT0()  asm volatile("cp.async.wait_group 0;" ::: "memory")

// activation column swizzle: px-group g (8 floats) lives at g*8 + (g>>2)*4
#define AROW 140
__device__ __forceinline__ int acol4(int v) {   // v = float4-index 0..31 (2 per group)
    int g = v >> 1;
    return g * 8 + (g >> 2) * 4 + (v & 1) * 4;
}

// ---------------------------------------------------------------------------
// Transpose w [B][NP][256(fg)] -> g_wt [B][256(fg)][NP], skipping K2 range
// ---------------------------------------------------------------------------
__global__ __launch_bounds__(256) void k_transpose(const float* __restrict__ w) {
    __shared__ float tile[32][33];
    int b = blockIdx.z;
    size_t base = (size_t)b * NP * 256;
    int g0 = blockIdx.x * 32;
    int y = blockIdx.y;
    int p0 = (y < 768) ? y * 32 : y * 32 + 3456;
    for (int i = threadIdx.y; i < 32; i += 8)
        tile[i][threadIdx.x] = w[base + (size_t)(p0 + i) * 256 + g0 + threadIdx.x];
    __syncthreads();
    for (int i = threadIdx.y; i < 32; i += 8)
        g_wt[base + (size_t)(g0 + i) * NP + p0 + threadIdx.x] = tile[threadIdx.x][i];
}

// ---------------------------------------------------------------------------
// Stage 1: 2 patches/CTA, 128 threads, thread tile 8o x 8px.
// xs (64c x 128px) static; weights streamed in 8-c chunks, cp.async
// double-buffered. ws rows interleave patches: row = o*2 + p, 12 floats.
// ---------------------------------------------------------------------------
#define WS1 1536   // floats per ws buffer (128 rows x 12)
__global__ __launch_bounds__(128, 4) void k_stage1(
    const float* __restrict__ x,
    const float* __restrict__ g1, const float* __restrict__ b1,
    const float* __restrict__ m1, const float* __restrict__ v1)
{
    extern __shared__ float smem[];
    float* xs = smem;                 // [64][140]  35.8KB
    float* ws = smem + 64 * AROW;     // 2 x 1536   12.3KB
    uint32_t ws_u32 = (uint32_t)__cvta_generic_to_shared(ws);

    int blk = blockIdx.x;             // 0..511
    int b = blk >> 7, pp = blk & 127;
    int pid0 = pp * 2, pid1 = pp * 2 + 1;
    int f = pid0 >> 4, gg0 = pid0 & 15;
    int y0 = f * 8, x0 = gg0 * 8;
    int tid = threadIdx.x;
    int i = tid >> 4, j = tid & 15;
    int patch_l = j >> 3;
    int cb = j * 8 + (j >> 2) * 4;

    const float* Wb0 = g_wt + (size_t)(b * NPATCH + pid0) * NP;
    const float* Wb1 = g_wt + (size_t)(b * NPATCH + pid1) * NP;

    auto fill_ws = [&](int cidx, int bsel) {
        int ot = cidx >> 3, ct = cidx & 7;
        #pragma unroll
        for (int t = 0; t < 2; t++) {
            int idx = tid + t * 128;            // 0..255
            int p = idx >> 7, rem = idx & 127;
            int o = rem >> 1, c4 = (rem & 1) * 4;
            const float* src = (p ? Wb1 : Wb0) + (ot * 64 + o) * 64 + ct * 8 + c4;
            cp16(ws_u32 + (uint32_t)(bsel * WS1 + (o * 2 + p) * 12 + c4) * 4, src);
        }
        CP_COMMIT();
    };

    fill_ws(0, 0);

    // load x for both patches: 64c x 128px (swizzled columns)
    for (int idx = tid; idx < 2048; idx += 128) {
        int c = idx >> 5, v = idx & 31;
        int pt = v >> 4, w4 = v & 15;
        int prow = w4 >> 1, q4 = (w4 & 1) * 4;
        *(float4*)&xs[c * AROW + acol4(v)] =
            *(const float4*)&x[(((size_t)b * CIN + c) * HH + y0 + prow) * WW + x0 + pt * 8 + q4];
    }

    unsigned long long acc[8][4];
    int bb = 0;
    for (int cidx = 0; cidx < 48; cidx++) {
        int ct = cidx & 7;
        if (ct == 0) {
            #pragma unroll
            for (int a = 0; a < 8; a++)
                #pragma unroll
                for (int p2 = 0; p2 < 4; p2++) acc[a][p2] = 0ULL;
        }
        CP_WAIT0();
        __syncthreads();
        if (cidx < 47) fill_ws(cidx + 1, bb ^ 1);

        const float* wsb = ws + bb * WS1;
        #pragma unroll
        for (int c4 = 0; c4 < 8; c4 += 4) {
            float4 wv[8];
            #pragma unroll
            for (int oo = 0; oo < 8; oo++)
                wv[oo] = *(const float4*)&wsb[((i + oo * 8) * 2 + patch_l) * 12 + c4];
            #pragma unroll
            for (int kk = 0; kk < 4; kk++) {
                const float* xr = &xs[(ct * 8 + c4 + kk) * AROW + cb];
                ulonglong2 xa = *(const ulonglong2*)xr;
                ulonglong2 xb = *(const ulonglong2*)(xr + 4);
                #pragma unroll
                for (int oo = 0; oo < 8; oo++) {
                    unsigned long long w2 = pack2(((const float*)&wv[oo])[kk]);
                    ffma2(acc[oo][0], xa.x, w2);
                    ffma2(acc[oo][1], xa.y, w2);
                    ffma2(acc[oo][2], xb.x, w2);
                    ffma2(acc[oo][3], xb.y, w2);
                }
            }
        }

        if (ct == 7) {
            int ot = cidx >> 3;
            int row = j & 7;
            #pragma unroll
            for (int oo = 0; oo < 8; oo++) {
                int o = ot * 64 + i + oo * 8;
                float inv = g1[o] * rsqrtf(v1[o] + EPSV);
                float sh  = b1[o] - m1[o] * inv;
                float r[8];
                #pragma unroll
                for (int p2 = 0; p2 < 4; p2++) unpack2(acc[oo][p2], r[p2 * 2], r[p2 * 2 + 1]);
                #pragma unroll
                for (int q = 0; q < 8; q++)
                    r[q] = fminf(fmaxf(r[q] * inv + sh, 0.f), 6.f);
                float* dst = &g_h1[(((size_t)b * HID + o) * HH + y0 + row) * WW + x0 + patch_l * 8];
                *(float4*)dst       = make_float4(r[0], r[1], r[2], r[3]);
                *(float4*)(dst + 4) = make_float4(r[4], r[5], r[6], r[7]);
            }
        }
        bb ^= 1;
    }
}

// ---------------------------------------------------------------------------
// Stage 2: per-patch depthwise 3x3 (reflect halo) + bn2 + relu6
// ---------------------------------------------------------------------------
__global__ __launch_bounds__(128) void k_stage2(
    const float* __restrict__ w,
    const float* __restrict__ g2, const float* __restrict__ b2,
    const float* __restrict__ m2, const float* __restrict__ v2)
{
    __shared__ float hs[16][10][10];
    __shared__ float ks[16][9];
    int blk = blockIdx.x;
    int b = blk >> 8, pid = blk & 255;
    int f = pid >> 4, g = pid & 15;
    int ch0 = blockIdx.y * 16;
    int tid = threadIdx.x;
    int y0 = f * 8, x0 = g * 8;
    int fg = f * 16 + g;

    for (int idx = tid; idx < 1600; idx += 128) {
        int cl = idx / 100;
        int rem = idx - cl * 100;
        int r = rem / 10, cc = rem - r * 10;
        int yy = y0 + r - 1;
        int xx = x0 + cc - 1;
        yy = yy < 0 ? -yy : (yy >= HH ? 2 * HH - 2 - yy : yy);
        xx = xx < 0 ? -xx : (xx >= WW ? 2 * WW - 2 - xx : xx);
        hs[cl][r][cc] = g_h1[(((size_t)b * HID + ch0 + cl) * HH + yy) * WW + xx];
    }
    for (int idx = tid; idx < 144; idx += 128) {
        int cl = idx / 9, t = idx - (idx / 9) * 9;
        ks[cl][t] = w[((size_t)b * NP + P2OFF + (ch0 + cl) * 9 + t) * 256 + fg];
    }
    __syncthreads();

    int cl = tid >> 3, p = tid & 7;
    int ch = ch0 + cl;
    float inv = g2[ch] * rsqrtf(v2[ch] + EPSV);
    float sh  = b2[ch] - m2[ch] * inv;

    float r[8];
    #pragma unroll
    for (int q = 0; q < 8; q++) {
        float acc = 0.f;
        #pragma unroll
        for (int dy = 0; dy < 3; dy++)
            #pragma unroll
            for (int dx = 0; dx < 3; dx++)
                acc += hs[cl][p + dy][q + dx] * ks[cl][dy * 3 + dx];
        r[q] = fminf(fmaxf(acc * inv + sh, 0.f), 6.f);
    }
    float* dst = &g_h2[((size_t)(b * NPATCH + pid) * HID + ch) * 64 + p * 8];
    *(float4*)dst       = make_float4(r[0], r[1], r[2], r[3]);
    *(float4*)(dst + 4) = make_float4(r[4], r[5], r[6], r[7]);
}

// ---------------------------------------------------------------------------
// Stage 3: 2 patches/CTA, k-chunks of 16 (24 chunks), cp.async double-buffered.
// Buffer = hs(16x140) + ws(128 rows x 20, row = co*2 + p). 38.4KB total smem.
// ---------------------------------------------------------------------------
#define HS3 2240               // 16 * AROW
#define WS3 2560               // 128 * 20
#define BUF3 (HS3 + WS3)       // 4800 floats per buffer
__global__ __launch_bounds__(128, 4) void k_stage3(
    const float* __restrict__ x,
    const float* __restrict__ g3, const float* __restrict__ b3,
    const float* __restrict__ m3, const float* __restrict__ v3,
    float* __restrict__ out)
{
    extern __shared__ float smem[];
    uint32_t smem_u32 = (uint32_t)__cvta_generic_to_shared(smem);

    int blk = blockIdx.x;             // 0..511
    int b = blk >> 7, pp = blk & 127;
    int pid0 = pp * 2, pid1 = pp * 2 + 1;
    int f = pid0 >> 4, gg0 = pid0 & 15;
    int y0 = f * 8, x0 = gg0 * 8;
    int tid = threadIdx.x;
    int i = tid >> 4, j = tid & 15;
    int patch_l = j >> 3;
    int cb = j * 8 + (j >> 2) * 4;

    const float* Wb0 = g_wt + (size_t)(b * NPATCH + pid0) * NP + P3OFF;
    const float* Wb1 = g_wt + (size_t)(b * NPATCH + pid1) * NP + P3OFF;
    const float* Hb0 = g_h2 + (size_t)(b * NPATCH + pid0) * HID * 64;
    const float* Hb1 = g_h2 + (size_t)(b * NPATCH + pid1) * HID * 64;

    auto fill3 = [&](int kt, int bsel) {
        uint32_t base = smem_u32 + (uint32_t)(bsel * BUF3) * 4;
        #pragma unroll
        for (int t = 0; t < 4; t++) {           // hs: 16k x 128px = 512 f4
            int idx = tid + t * 128;
            int k = idx >> 5, v = idx & 31;
            int pt = v >> 4, w4 = v & 15;
            const float* src = (pt ? Hb1 : Hb0) + (kt * 16 + k) * 64 + w4 * 4;
            cp16(base + (uint32_t)(k * AROW + acol4(v)) * 4, src);
        }
        #pragma unroll
        for (int t = 0; t < 4; t++) {           // ws: 2 x 64co x 16k = 512 f4
            int idx = tid + t * 128;
            int p = idx >> 8, rem = idx & 255;
            int co = rem >> 2, c4 = (rem & 3) * 4;
            const float* src = (p ? Wb1 : Wb0) + co * HID + kt * 16 + c4;
            cp16(base + (uint32_t)(HS3 + (co * 2 + p) * 20 + c4) * 4, src);
        }
        CP_COMMIT();
    };

    fill3(0, 0);

    unsigned long long acc[8][4];
    #pragma unroll
    for (int a = 0; a < 8; a++)
        #pragma unroll
        for (int p2 = 0; p2 < 4; p2++) acc[a][p2] = 0ULL;

    int bb = 0;
    for (int kt = 0; kt < 24; kt++) {
        CP_WAIT0();
        __syncthreads();
        if (kt < 23) fill3(kt + 1, bb ^ 1);

        const float* hsb = smem + bb * BUF3;
        const float* wsb = hsb + HS3;
        #pragma unroll
        for (int c4 = 0; c4 < 16; c4 += 4) {
            float4 wv[8];
            #pragma unroll
            for (int oo = 0; oo < 8; oo++)
                wv[oo] = *(const float4*)&wsb[((i + oo * 8) * 2 + patch_l) * 20 + c4];
            #pragma unroll
            for (int kk = 0; kk < 4; kk++) {
                const float* xr = &hsb[(c4 + kk) * AROW + cb];
                ulonglong2 xa = *(const ulonglong2*)xr;
                ulonglong2 xb = *(const ulonglong2*)(xr + 4);
                #pragma unroll
                for (int oo = 0; oo < 8; oo++) {
                    unsigned long long w2 = pack2(((const float*)&wv[oo])[kk]);
                    ffma2(acc[oo][0], xa.x, w2);
                    ffma2(acc[oo][1], xa.y, w2);
                    ffma2(acc[oo][2], xb.x, w2);
                    ffma2(acc[oo][3], xb.y, w2);
                }
            }
        }
        bb ^= 1;
    }

    int row = j & 7;
    #pragma unroll
    for (int oo = 0; oo < 8; oo++) {
        int co = i + oo * 8;
        float inv = g3[co] * rsqrtf(v3[co] + EPSV);
        float sh  = b3[co] - m3[co] * inv;
        float r[8];
        #pragma unroll
        for (int p2 = 0; p2 < 4; p2++) unpack2(acc[oo][p2], r[p2 * 2], r[p2 * 2 + 1]);
        size_t base = (((size_t)b * COUT + co) * HH + y0 + row) * WW + x0 + patch_l * 8;
        float4 xr0 = *(const float4*)&x[base];
        float4 xr1 = *(const float4*)&x[base + 4];
        float4 o0 = make_float4(xr0.x + (r[0] * inv + sh), xr0.y + (r[1] * inv + sh),
                                xr0.z + (r[2] * inv + sh), xr0.w + (r[3] * inv + sh));
        float4 o1 = make_float4(xr1.x + (r[4] * inv + sh), xr1.y + (r[5] * inv + sh),
                                xr1.z + (r[6] * inv + sh), xr1.w + (r[7] * inv + sh));
        *(float4*)&out[base]     = o0;
        *(float4*)&out[base + 4] = o1;
    }
}

// ---------------------------------------------------------------------------
extern "C" void kernel_launch(void* const* d_in, const int* in_sizes, int n_in,
                              void* d_out, int out_size) {
    const float* x  = (const float*)d_in[0];
    const float* w  = (const float*)d_in[1];
    const float* g1 = (const float*)d_in[2];
    const float* b1 = (const float*)d_in[3];
    const float* m1 = (const float*)d_in[4];
    const float* v1 = (const float*)d_in[5];
    const float* g2 = (const float*)d_in[6];
    const float* b2 = (const float*)d_in[7];
    const float* m2 = (const float*)d_in[8];
    const float* v2 = (const float*)d_in[9];
    const float* g3 = (const float*)d_in[10];
    const float* b3 = (const float*)d_in[11];
    const float* m3 = (const float*)d_in[12];
    const float* v3 = (const float*)d_in[13];
    float* out = (float*)d_out;

    const int S1_SMEM = (64 * AROW + 2 * WS1) * 4;   // 48128
    const int S3_SMEM = (2 * BUF3) * 4;              // 38400
    cudaFuncSetAttribute(k_stage1, cudaFuncAttributeMaxDynamicSharedMemorySize, S1_SMEM);
    cudaFuncSetAttribute(k_stage3, cudaFuncAttributeMaxDynamicSharedMemorySize, S3_SMEM);

    dim3 tb(32, 8);
    dim3 tg(256 / 32, 1536, BB);   // K2 param range skipped
    k_transpose<<<tg, tb>>>(w);
    k_stage1<<<BB * NPATCH / 2, 128, S1_SMEM>>>(x, g1, b1, m1, v1);
    k_stage2<<<dim3(BB * NPATCH, HID / 16), 128>>>(w, g2, b2, m2, v2);
    k_stage3<<<BB * NPATCH / 2, 128, S3_SMEM>>>(x, g3, b3, m3, v3, out);
}